// round 11
// baseline (speedup 1.0000x reference)
#include <cuda_runtime.h>

// ---------------- problem constants ----------------
#define Bq   256
#define Tq   128
#define AD   8
#define ZD   32
#define KM   16
#define HIDq 50
#define BT   (Bq*Tq)

// ---------------- device scratch ----------------
__device__ float g_w[BT*KM];
__device__ float g_sigf[(size_t)BT*1024];   // Sigma_f[t]
__device__ float g_T1s[(size_t)BT*1024];    // T1 = A_{t+1} Sigma_f[t]   (slot t, t<=T-2)
__device__ float g_sp[(size_t)BT*1024];     // Sigma_pred[t+1]           (slot t, t<=T-2)
__device__ float g_X[(size_t)BT*1024];      // X = sp^{-1} T1 (= J^T)    (slot t, t<=T-2)
__device__ float g_muf[BT*ZD];              // mu_f[t]
__device__ float g_mp[BT*ZD];               // mu_pred[t+1]              (slot t, t<=T-2)

// =====================================================================
// Kernel 1: LSTM over T + softmax mixture weights (verified, unchanged).
// =====================================================================
__global__ void __launch_bounds__(256)
lstm_kernel(const float* __restrict__ a,  const float* __restrict__ a1,
            const float* __restrict__ W_ih, const float* __restrict__ W_hh,
            const float* __restrict__ b_ih, const float* __restrict__ b_hh,
            const float* __restrict__ W_alpha, const float* __restrict__ b_alpha)
{
    __shared__ float sWhh[HIDq*200];     // transposed: [j][g]
    __shared__ float sWa[KM*HIDq];
    __shared__ float sh[HIDq], sc[HIDq], sx[AD], sg[200];

    const int b = blockIdx.x, tid = threadIdx.x;

    float wi[AD]; float bg = 0.f;
    if (tid < 200) {
        #pragma unroll
        for (int j = 0; j < AD; j++) wi[j] = W_ih[tid*AD + j];
        bg = b_ih[tid] + b_hh[tid];
    }
    for (int i = tid; i < 200*HIDq; i += 256) {
        int g = i / HIDq, j = i % HIDq;
        sWhh[j*200 + g] = W_hh[i];
    }
    for (int i = tid; i < KM*HIDq; i += 256) sWa[i] = W_alpha[i];
    if (tid < HIDq) { sh[tid] = 0.f; sc[tid] = 0.f; }
    __syncthreads();

    for (int t = 0; t < Tq; t++) {
        if (tid < AD) sx[tid] = (t == 0) ? a1[tid] : a[(b*Tq + (t-1))*AD + tid];
        __syncthreads();                 // B1
        if (tid < 200) {
            float a0 = bg, a1_ = 0.f, a2 = 0.f, a3 = 0.f;
            #pragma unroll
            for (int j = 0; j < AD; j++) a0 += sx[j]*wi[j];
            #pragma unroll
            for (int j = 0; j < 48; j += 4) {
                a0  += sh[j  ]*sWhh[(j  )*200 + tid];
                a1_ += sh[j+1]*sWhh[(j+1)*200 + tid];
                a2  += sh[j+2]*sWhh[(j+2)*200 + tid];
                a3  += sh[j+3]*sWhh[(j+3)*200 + tid];
            }
            a0  += sh[48]*sWhh[48*200 + tid];
            a1_ += sh[49]*sWhh[49*200 + tid];
            sg[tid] = (a0 + a1_) + (a2 + a3);
        }
        __syncthreads();                 // B2
        if (tid < HIDq) {
            float ig = 1.f/(1.f + __expf(-sg[tid]));
            float fg = 1.f/(1.f + __expf(-sg[HIDq + tid]));
            float gg = tanhf(sg[2*HIDq + tid]);
            float og = 1.f/(1.f + __expf(-sg[3*HIDq + tid]));
            float c  = fg*sc[tid] + ig*gg;
            sc[tid] = c;
            sh[tid] = og*tanhf(c);
        }
        __syncthreads();                 // B3
        if (tid < 32) {
            float logit = -1e30f;
            if (tid < KM) {
                logit = b_alpha[tid];
                #pragma unroll
                for (int j = 0; j < HIDq; j++) logit += sh[j]*sWa[tid*HIDq + j];
            }
            float m = logit;
            #pragma unroll
            for (int d = 8; d; d >>= 1)
                m = fmaxf(m, __shfl_xor_sync(0xffffffffu, m, d, 16));
            float e = __expf(logit - m);
            float s = e;
            #pragma unroll
            for (int d = 8; d; d >>= 1)
                s += __shfl_xor_sync(0xffffffffu, s, d, 16);
            if (tid < KM) g_w[(b*Tq + t)*KM + tid] = e/s;
        }
    }
}

// =====================================================================
// Kernel 2: A_t/C_t mixing (verified, unchanged).
// =====================================================================
__global__ void __launch_bounds__(256)
mix_kernel(const float* __restrict__ Ag, const float* __restrict__ Cg,
           float* __restrict__ outA, float* __restrict__ outC)
{
    __shared__ float sw[128*KM];
    const int tid = threadIdx.x;
    const int r0  = blockIdx.x * 128;
    for (int i = tid; i < 128*KM; i += 256) sw[i] = g_w[r0*KM + i];
    __syncthreads();

    for (int c = tid; c < 1280; c += 256) {
        float av[KM];
        if (c < 1024) {
            #pragma unroll
            for (int k = 0; k < KM; k++) av[k] = Ag[k*1024 + c];
            for (int r = 0; r < 128; r++) {
                float acc = 0.f;
                #pragma unroll
                for (int k = 0; k < KM; k++) acc += sw[r*KM + k]*av[k];
                outA[(size_t)(r0 + r)*1024 + c] = acc;
            }
        } else {
            const int cc = c - 1024;
            #pragma unroll
            for (int k = 0; k < KM; k++) av[k] = Cg[k*256 + cc];
            for (int r = 0; r < 128; r++) {
                float acc = 0.f;
                #pragma unroll
                for (int k = 0; k < KM; k++) acc += sw[r*KM + k]*av[k];
                outC[(r0 + r)*256 + cc] = acc;
            }
        }
    }
}

// =====================================================================
// Kernel 3: Kalman forward filter — round-10 verified math, TWO batches
// per CTA (grid Bq/2 = 128, one CTA per SM). Pure duplication: every
// phase processes instances u=0,1 with identical per-output arithmetic;
// the two 8x8 inversions run on warp 0 / warp 1. Same 8 barriers/step.
// Kg comes from Pt (rows of sigp) — load-bearing for stability.
// =====================================================================
__global__ void __launch_bounds__(256)
fwd_kernel(const float* __restrict__ a,
           float* __restrict__ out_mu, float* __restrict__ out_sig,
           const float* __restrict__ outA, const float* __restrict__ outC)
{
    __shared__ float sAbuf[2][2*1056];              // [u] ping-pong A (stride 33)
    __shared__ float sC[2][256];                    // [u] C_t [8][32]
    __shared__ float sigp[2][1056];                 // [u] sig_pred (stride 33)
    __shared__ __align__(16) float sigf[2][1024];   // [u] sig_filt (stride 32)
    __shared__ float big[2][1024];                  // [u] M1 | Pt | KgT | aug8
    __shared__ __align__(16) float T1b[2][32*36];   // [u] T1 (stride 36)
    __shared__ float sAmu[2][ZD], serr[2][AD], smu[2][ZD];

    const int tid = threadIdx.x;
    const int b0 = blockIdx.x*2;            // batches b0, b0+1
    const int i4 = tid >> 3;                // tiled-output row (0..31)
    const int jb = (tid & 7) << 2;          // tiled-output col block (x4)

    // ---- init: sig_pred = 20*I, mu = 0, load A_t[b][0] ----
    #pragma unroll
    for (int u = 0; u < 2; u++) {
        for (int e = tid; e < 1024; e += 256) {
            int i = e >> 5, j = e & 31;
            sigp[u][i*33 + j] = (i == j) ? 20.f : 0.f;
            sAbuf[u][i*33 + j] = outA[(size_t)((b0 + u)*Tq)*1024 + e];
        }
        if (tid < ZD) smu[u][tid] = 0.f;
    }
    __syncthreads();

    for (int t = 0; t < Tq; t++) {
        const int pp = t & 1, pn = (t + 1) & 1;
        const size_t bt0 = (size_t)b0*Tq + t;
        const size_t bt1 = bt0 + Tq;

        // B1 phase: sC loads (both) + Amu = Ac @ mu (tid<64, u = tid>>5)
        sC[0][tid] = outC[bt0*256 + tid];
        sC[1][tid] = outC[bt1*256 + tid];
        if (tid < 64) {
            int u = tid >> 5, i = tid & 31;
            const float* Ac = sAbuf[u] + pp*1056;
            float acc = 0.f;
            #pragma unroll
            for (int m = 0; m < 32; m++) acc += Ac[i*33 + m]*smu[u][m];
            sAmu[u][i] = acc;
            if (t > 0) g_mp[((u ? bt1 : bt0) - 1)*ZD + i] = acc;
        }
        __syncthreads();   // B1

        // B2 phase: M1 = C @ sigp ; Pt[l][i] = (sigp C^T)[i][l]  (both u)
        {
            int l = tid >> 5, j = tid & 31;
            #pragma unroll
            for (int u = 0; u < 2; u++) {
                float acc = 0.f;
                #pragma unroll
                for (int m = 0; m < 32; m++) acc += sC[u][l*32 + m]*sigp[u][m*33 + j];
                big[u][l*32 + j] = acc;
                float acc2 = 0.f;
                #pragma unroll
                for (int m = 0; m < 32; m++) acc2 += sigp[u][j*33 + m]*sC[u][l*32 + m];
                big[u][256 + l*32 + j] = acc2;
            }
        }
        __syncthreads();   // B2

        // B3 phase: S aug (tid<128, u = tid>>6) | err (tid 128..143)
        if (tid < 128) {
            int u = tid >> 6, r = tid & 63;
            int l = r >> 3, n = r & 7;
            float acc = 0.f;
            #pragma unroll
            for (int m = 0; m < 32; m++) acc += big[u][l*32 + m]*sC[u][n*32 + m];
            big[u][768 + l*16 + n]     = acc + ((l == n) ? 0.03f : 0.f);
            big[u][768 + l*16 + 8 + n] = (l == n) ? 1.f : 0.f;
        } else if (tid < 144) {
            int u = (tid - 128) >> 3, l = (tid - 128) & 7;
            float acc = 0.f;
            #pragma unroll
            for (int m = 0; m < 32; m++) acc += sC[u][l*32 + m]*sAmu[u][m];
            serr[u][l] = a[(u ? bt1 : bt0)*AD + l] - acc;
        }
        __syncthreads();   // B3

        // B4 phase: invert both 8x8 SPDs (warp 0 -> u=0, warp 1 -> u=1)
        if (tid < 64) {
            int u = tid >> 5, lane = tid & 31;
            float* Sg = big[u] + 768;
            int r = lane >> 2, c0 = (lane & 3)*4;
            #pragma unroll
            for (int p = 0; p < 8; p++) {
                float fc = Sg[r*16 + p];
                float p0 = Sg[p*16 + c0];
                float p1 = Sg[p*16 + c0 + 1];
                float p2 = Sg[p*16 + c0 + 2];
                float p3 = Sg[p*16 + c0 + 3];
                float pd = Sg[p*16 + p];
                __syncwarp();
                float pinv = 1.f/pd;
                if (r == p) {
                    Sg[r*16 + c0]     = p0*pinv;
                    Sg[r*16 + c0 + 1] = p1*pinv;
                    Sg[r*16 + c0 + 2] = p2*pinv;
                    Sg[r*16 + c0 + 3] = p3*pinv;
                } else {
                    float f = fc*pinv;
                    Sg[r*16 + c0]     -= f*p0;
                    Sg[r*16 + c0 + 1] -= f*p1;
                    Sg[r*16 + c0 + 2] -= f*p2;
                    Sg[r*16 + c0 + 3] -= f*p3;
                }
                __syncwarp();
            }
        }
        __syncthreads();   // B4

        // B5 phase: Kg^T[l][i] = sum_n Pt[n][i] * Sinv[n][l]  (both u)
        {
            int l = tid >> 5, i = tid & 31;
            #pragma unroll
            for (int u = 0; u < 2; u++) {
                float acc = 0.f;
                #pragma unroll
                for (int n = 0; n < 8; n++)
                    acc += big[u][256 + n*32 + i]*big[u][768 + n*16 + 8 + l];
                big[u][512 + l*32 + i] = acc;
            }
        }
        __syncthreads();   // B5

        // B6 phase: sig_f = sigp - Kg @ M1 + prefetch A_{t+1} (both u)
        //           + mu_f (tid<64, u = tid>>5)
        #pragma unroll
        for (int q = 0; q < 8; q++) {
            int e = tid + 256*q;            // 0..2047
            int u = e >> 10, e1 = e & 1023;
            int i = e1 >> 5, j = e1 & 31;
            const size_t bt = u ? bt1 : bt0;
            float v = sigp[u][i*33 + j];
            #pragma unroll
            for (int l = 0; l < 8; l++) v -= big[u][512 + l*32 + i]*big[u][l*32 + j];
            sigf[u][e1] = v;
            g_sigf[bt*1024 + e1] = v;
            if (t == Tq - 1) out_sig[bt*1024 + e1] = v;
            if (t < Tq - 1)
                sAbuf[u][pn*1056 + i*33 + j] = outA[(bt + 1)*1024 + e1];
        }
        if (tid < 64) {
            int u = tid >> 5, i = tid & 31;
            const size_t bt = u ? bt1 : bt0;
            float v = sAmu[u][i];
            #pragma unroll
            for (int l = 0; l < 8; l++) v += big[u][512 + l*32 + i]*serr[u][l];
            smu[u][i] = v;
            g_muf[bt*ZD + i] = v;
            if (t == Tq - 1) out_mu[bt*ZD + i] = v;
        }
        __syncthreads();   // B6

        if (t < Tq - 1) {
            // B7 phase (tiled): T1 = A_n @ sig_f (both u)
            #pragma unroll
            for (int u = 0; u < 2; u++) {
                const float* Anx = sAbuf[u] + pn*1056;
                float x0 = 0.f, x1 = 0.f, x2 = 0.f, x3 = 0.f;
                #pragma unroll
                for (int m = 0; m < 32; m++) {
                    float av = Anx[i4*33 + m];
                    const float4 s = *(const float4*)&sigf[u][m*32 + jb];
                    x0 += av*s.x; x1 += av*s.y; x2 += av*s.z; x3 += av*s.w;
                }
                T1b[u][i4*36 + jb]     = x0;
                T1b[u][i4*36 + jb + 1] = x1;
                T1b[u][i4*36 + jb + 2] = x2;
                T1b[u][i4*36 + jb + 3] = x3;
                float4 r = {x0, x1, x2, x3};
                *(float4*)(g_T1s + (u ? bt1 : bt0)*1024 + i4*32 + jb) = r;
            }
            __syncthreads();   // B7

            // B8 phase (tiled): sigp = T1 @ A_n^T + Q (both u)
            #pragma unroll
            for (int u = 0; u < 2; u++) {
                const float* Anx = sAbuf[u] + pn*1056;
                float a0 = (i4 == jb    ) ? 0.08f : 0.f;
                float a1 = (i4 == jb + 1) ? 0.08f : 0.f;
                float a2 = (i4 == jb + 2) ? 0.08f : 0.f;
                float a3 = (i4 == jb + 3) ? 0.08f : 0.f;
                #pragma unroll
                for (int m4 = 0; m4 < 32; m4 += 4) {
                    const float4 t4 = *(const float4*)&T1b[u][i4*36 + m4];
                    a0 += t4.x*Anx[(jb    )*33 + m4]     + t4.y*Anx[(jb    )*33 + m4 + 1]
                        + t4.z*Anx[(jb    )*33 + m4 + 2] + t4.w*Anx[(jb    )*33 + m4 + 3];
                    a1 += t4.x*Anx[(jb + 1)*33 + m4]     + t4.y*Anx[(jb + 1)*33 + m4 + 1]
                        + t4.z*Anx[(jb + 1)*33 + m4 + 2] + t4.w*Anx[(jb + 1)*33 + m4 + 3];
                    a2 += t4.x*Anx[(jb + 2)*33 + m4]     + t4.y*Anx[(jb + 2)*33 + m4 + 1]
                        + t4.z*Anx[(jb + 2)*33 + m4 + 2] + t4.w*Anx[(jb + 2)*33 + m4 + 3];
                    a3 += t4.x*Anx[(jb + 3)*33 + m4]     + t4.y*Anx[(jb + 3)*33 + m4 + 1]
                        + t4.z*Anx[(jb + 3)*33 + m4 + 2] + t4.w*Anx[(jb + 3)*33 + m4 + 3];
                }
                sigp[u][i4*33 + jb]     = a0;
                sigp[u][i4*33 + jb + 1] = a1;
                sigp[u][i4*33 + jb + 2] = a2;
                sigp[u][i4*33 + jb + 3] = a3;
                float4 r = {a0, a1, a2, a3};
                *(float4*)(g_sp + (u ? bt1 : bt0)*1024 + i4*32 + jb) = r;
            }
            __syncthreads();   // B8
        }
    }
}

// =====================================================================
// Kernel 4: batched solves X = sp^{-1} T1 (round-10 verified, unchanged).
// =====================================================================
__global__ void __launch_bounds__(256)
solve_kernel()
{
    const int lin = blockIdx.x;             // 0 .. Bq*(Tq-1)-1
    const int b = lin / (Tq - 1), t = lin % (Tq - 1);
    const size_t bt = (size_t)b*Tq + t;
    const int tid = threadIdx.x;
    const int c = tid >> 2, q = tid & 3;

    __shared__ float Tsh[32*33];
    __shared__ float sfac[2][32];
    __shared__ float spinv[2];

    // stage T1 coalesced -> shared (stride 33; STS conflict-free)
    #pragma unroll
    for (int k = 0; k < 4; k++) {
        int e = tid + 256*k, i = e >> 5, j = e & 31;
        Tsh[i*33 + j] = g_T1s[bt*1024 + e];
    }

    float reg[8];
    if (c < 32) {
        // sp symmetric: column c == row c (contiguous) -> 2 float4 loads
        const float4* bp = (const float4*)(g_sp + bt*1024 + c*32 + q*8);
        float4 r0 = bp[0], r1 = bp[1];
        reg[0] = r0.x; reg[1] = r0.y; reg[2] = r0.z; reg[3] = r0.w;
        reg[4] = r1.x; reg[5] = r1.y; reg[6] = r1.z; reg[7] = r1.w;
    }
    // pivot-0 prep: column 0 snapshot + reciprocal
    if (c == 0) {
        #pragma unroll
        for (int i = 0; i < 8; i++) sfac[0][q*8 + i] = reg[i];
        if (q == 0) spinv[0] = 1.f/reg[0];
    }
    __syncthreads();
    if (c >= 32) {
        // column (c-32) of T1 from padded shared (LDS conflict-free)
        #pragma unroll
        for (int i = 0; i < 8; i++) reg[i] = Tsh[(q*8 + i)*33 + (c - 32)];
    }

    #pragma unroll
    for (int p = 0; p < 32; p++) {
        const int pb = p & 1;
        const float piv = spinv[pb];
        float fac[8];
        #pragma unroll
        for (int i = 0; i < 8; i++) fac[i] = sfac[pb][q*8 + i];
        // row-p element of my column (pre-update), from the lane with q = p>>3
        float m_pc = __shfl_sync(0xffffffffu, reg[p & 7], p >> 3, 4);
        float mn = m_pc * piv;
        if (c > p) {
            #pragma unroll
            for (int i = 0; i < 8; i++) {
                int r = q*8 + i;
                reg[i] = (r == p) ? mn : (reg[i] - fac[i]*mn);
            }
            if (p < 31 && c == p + 1) {
                #pragma unroll
                for (int i = 0; i < 8; i++) sfac[pb ^ 1][q*8 + i] = reg[i];
                if (q == ((p + 1) >> 3)) spinv[pb ^ 1] = 1.f/reg[(p + 1) & 7];
            }
        }
        __syncthreads();
    }

    // stage X through shared (conflict-free STS), write coalesced
    if (c >= 32) {
        #pragma unroll
        for (int i = 0; i < 8; i++) Tsh[(q*8 + i)*33 + (c - 32)] = reg[i];
    }
    __syncthreads();
    #pragma unroll
    for (int k = 0; k < 4; k++) {
        int e = tid + 256*k, i = e >> 5, j = e & 31;
        g_X[bt*1024 + e] = Tsh[i*33 + j];
    }
}

// =====================================================================
// Kernel 5: RTS backward (verified, unchanged).
// =====================================================================
__global__ void __launch_bounds__(256)
bwd_kernel(float* __restrict__ out_mu, float* __restrict__ out_sig)
{
    __shared__ __align__(16) float X[1024], D[1024], G[1024], Ssn[1024];
    __shared__ float sdm[ZD], smf[ZD], sxv[ZD], smusn[ZD];

    const int b = blockIdx.x, tid = threadIdx.x;
    const int i4 = tid >> 3, jb = (tid & 7) << 2;

    {
        const size_t bt = (size_t)b*Tq + (Tq - 1);
        ((float4*)Ssn)[tid] = ((const float4*)(g_sigf + bt*1024))[tid];
        if (tid < ZD) smusn[tid] = g_muf[bt*ZD + tid];
    }
    __syncthreads();

    for (int t = Tq - 2; t >= 0; t--) {
        const size_t bt = (size_t)b*Tq + t;
        // pass0: loads
        ((float4*)X)[tid] = ((const float4*)(g_X + bt*1024))[tid];
        {
            float4 s = ((const float4*)Ssn)[tid];
            float4 p = ((const float4*)(g_sp + bt*1024))[tid];
            float4 d = {s.x - p.x, s.y - p.y, s.z - p.z, s.w - p.w};
            ((float4*)D)[tid] = d;
        }
        if (tid < ZD) {
            sdm[tid] = smusn[tid] - g_mp[bt*ZD + tid];
            smf[tid] = g_muf[bt*ZD + tid];
        }
        __syncthreads();

        // pass A: G = D @ X ; xv = X^T dm
        {
            float g0 = 0, g1 = 0, g2 = 0, g3 = 0;
            #pragma unroll
            for (int m = 0; m < 32; m++) {
                float dv = D[i4*32 + m];
                const float4 xm = *(const float4*)&X[m*32 + jb];
                g0 += dv*xm.x; g1 += dv*xm.y; g2 += dv*xm.z; g3 += dv*xm.w;
            }
            G[i4*32 + jb] = g0; G[i4*32 + jb + 1] = g1;
            G[i4*32 + jb + 2] = g2; G[i4*32 + jb + 3] = g3;
        }
        if (tid < ZD) {
            float v = 0.f;
            #pragma unroll
            for (int k = 0; k < 32; k++) v += X[k*32 + tid]*sdm[k];
            sxv[tid] = v;
        }
        __syncthreads();

        // pass B: sig_s = sf + X^T G ; mu_s = mf + xv
        {
            float4 acc = ((const float4*)(g_sigf + bt*1024))[tid];
            #pragma unroll
            for (int k = 0; k < 32; k++) {
                float xk = X[k*32 + i4];
                const float4 g4 = *(const float4*)&G[k*32 + jb];
                acc.x += xk*g4.x; acc.y += xk*g4.y; acc.z += xk*g4.z; acc.w += xk*g4.w;
            }
            ((float4*)(out_sig + bt*1024))[tid] = acc;
            ((float4*)Ssn)[tid] = acc;
        }
        if (tid < ZD) {
            float v = smf[tid] + sxv[tid];
            out_mu[bt*ZD + tid] = v;
            smusn[tid] = v;
        }
        __syncthreads();
    }
}

// =====================================================================
extern "C" void kernel_launch(void* const* d_in, const int* in_sizes, int n_in,
                              void* d_out, int out_size)
{
    const float* a       = (const float*)d_in[0];
    const float* a1      = (const float*)d_in[1];
    const float* W_ih    = (const float*)d_in[2];
    const float* W_hh    = (const float*)d_in[3];
    const float* b_ih    = (const float*)d_in[4];
    const float* b_hh    = (const float*)d_in[5];
    const float* W_alpha = (const float*)d_in[6];
    const float* b_alpha = (const float*)d_in[7];
    const float* Ag      = (const float*)d_in[8];
    const float* Cg      = (const float*)d_in[9];

    float* out    = (float*)d_out;
    float* out_mu = out;                              // [B,T,32]
    float* out_sg = out_mu + (size_t)BT*ZD;           // [B,T,32,32]
    float* out_A  = out_sg + (size_t)BT*ZD*ZD;        // [B,T,32,32]
    float* out_C  = out_A  + (size_t)BT*ZD*ZD;        // [B,T,8,32]

    lstm_kernel<<<Bq, 256>>>(a, a1, W_ih, W_hh, b_ih, b_hh, W_alpha, b_alpha);
    mix_kernel<<<BT/128, 256>>>(Ag, Cg, out_A, out_C);
    fwd_kernel<<<Bq/2, 256>>>(a, out_mu, out_sg, out_A, out_C);
    solve_kernel<<<Bq*(Tq - 1), 256>>>();
    bwd_kernel<<<Bq, 256>>>(out_mu, out_sg);
}

// round 12
// speedup vs baseline: 1.1136x; 1.1136x over previous
#include <cuda_runtime.h>

// ---------------- problem constants ----------------
#define Bq   256
#define Tq   128
#define AD   8
#define ZD   32
#define KM   16
#define HIDq 50
#define BT   (Bq*Tq)

// ---------------- device scratch ----------------
__device__ float g_w[BT*KM];
__device__ float g_sigf[(size_t)BT*1024];   // Sigma_f[t]
__device__ float g_T1s[(size_t)BT*1024];    // T1 = A_{t+1} Sigma_f[t]   (slot t, t<=T-2)
__device__ float g_sp[(size_t)BT*1024];     // Sigma_pred[t+1]           (slot t, t<=T-2)
__device__ float g_X[(size_t)BT*1024];      // X = sp^{-1} T1 (= J^T)    (slot t, t<=T-2)
__device__ float g_muf[BT*ZD];              // mu_f[t]
__device__ float g_mp[BT*ZD];               // mu_pred[t+1]              (slot t, t<=T-2)

// =====================================================================
// Kernel 1: LSTM over T + softmax mixture weights (verified, unchanged).
// =====================================================================
__global__ void __launch_bounds__(256)
lstm_kernel(const float* __restrict__ a,  const float* __restrict__ a1,
            const float* __restrict__ W_ih, const float* __restrict__ W_hh,
            const float* __restrict__ b_ih, const float* __restrict__ b_hh,
            const float* __restrict__ W_alpha, const float* __restrict__ b_alpha)
{
    __shared__ float sWhh[HIDq*200];     // transposed: [j][g]
    __shared__ float sWa[KM*HIDq];
    __shared__ float sh[HIDq], sc[HIDq], sx[AD], sg[200];

    const int b = blockIdx.x, tid = threadIdx.x;

    float wi[AD]; float bg = 0.f;
    if (tid < 200) {
        #pragma unroll
        for (int j = 0; j < AD; j++) wi[j] = W_ih[tid*AD + j];
        bg = b_ih[tid] + b_hh[tid];
    }
    for (int i = tid; i < 200*HIDq; i += 256) {
        int g = i / HIDq, j = i % HIDq;
        sWhh[j*200 + g] = W_hh[i];
    }
    for (int i = tid; i < KM*HIDq; i += 256) sWa[i] = W_alpha[i];
    if (tid < HIDq) { sh[tid] = 0.f; sc[tid] = 0.f; }
    __syncthreads();

    for (int t = 0; t < Tq; t++) {
        if (tid < AD) sx[tid] = (t == 0) ? a1[tid] : a[(b*Tq + (t-1))*AD + tid];
        __syncthreads();                 // B1
        if (tid < 200) {
            float a0 = bg, a1_ = 0.f, a2 = 0.f, a3 = 0.f;
            #pragma unroll
            for (int j = 0; j < AD; j++) a0 += sx[j]*wi[j];
            #pragma unroll
            for (int j = 0; j < 48; j += 4) {
                a0  += sh[j  ]*sWhh[(j  )*200 + tid];
                a1_ += sh[j+1]*sWhh[(j+1)*200 + tid];
                a2  += sh[j+2]*sWhh[(j+2)*200 + tid];
                a3  += sh[j+3]*sWhh[(j+3)*200 + tid];
            }
            a0  += sh[48]*sWhh[48*200 + tid];
            a1_ += sh[49]*sWhh[49*200 + tid];
            sg[tid] = (a0 + a1_) + (a2 + a3);
        }
        __syncthreads();                 // B2
        if (tid < HIDq) {
            float ig = 1.f/(1.f + __expf(-sg[tid]));
            float fg = 1.f/(1.f + __expf(-sg[HIDq + tid]));
            float gg = tanhf(sg[2*HIDq + tid]);
            float og = 1.f/(1.f + __expf(-sg[3*HIDq + tid]));
            float c  = fg*sc[tid] + ig*gg;
            sc[tid] = c;
            sh[tid] = og*tanhf(c);
        }
        __syncthreads();                 // B3
        if (tid < 32) {
            float logit = -1e30f;
            if (tid < KM) {
                logit = b_alpha[tid];
                #pragma unroll
                for (int j = 0; j < HIDq; j++) logit += sh[j]*sWa[tid*HIDq + j];
            }
            float m = logit;
            #pragma unroll
            for (int d = 8; d; d >>= 1)
                m = fmaxf(m, __shfl_xor_sync(0xffffffffu, m, d, 16));
            float e = __expf(logit - m);
            float s = e;
            #pragma unroll
            for (int d = 8; d; d >>= 1)
                s += __shfl_xor_sync(0xffffffffu, s, d, 16);
            if (tid < KM) g_w[(b*Tq + t)*KM + tid] = e/s;
        }
    }
}

// =====================================================================
// Kernel 2: A_t/C_t mixing (verified, unchanged).
// =====================================================================
__global__ void __launch_bounds__(256)
mix_kernel(const float* __restrict__ Ag, const float* __restrict__ Cg,
           float* __restrict__ outA, float* __restrict__ outC)
{
    __shared__ float sw[128*KM];
    const int tid = threadIdx.x;
    const int r0  = blockIdx.x * 128;
    for (int i = tid; i < 128*KM; i += 256) sw[i] = g_w[r0*KM + i];
    __syncthreads();

    for (int c = tid; c < 1280; c += 256) {
        float av[KM];
        if (c < 1024) {
            #pragma unroll
            for (int k = 0; k < KM; k++) av[k] = Ag[k*1024 + c];
            for (int r = 0; r < 128; r++) {
                float acc = 0.f;
                #pragma unroll
                for (int k = 0; k < KM; k++) acc += sw[r*KM + k]*av[k];
                outA[(size_t)(r0 + r)*1024 + c] = acc;
            }
        } else {
            const int cc = c - 1024;
            #pragma unroll
            for (int k = 0; k < KM; k++) av[k] = Cg[k*256 + cc];
            for (int r = 0; r < 128; r++) {
                float acc = 0.f;
                #pragma unroll
                for (int k = 0; k < KM; k++) acc += sw[r*KM + k]*av[k];
                outC[(r0 + r)*256 + cc] = acc;
            }
        }
    }
}

// =====================================================================
// Kernel 3: Kalman forward filter — round-10 verified math, REVERTED to
// one batch per CTA (grid = Bq; intra-CTA batching regressed). ONE new
// change: B1 phase removed (7 barriers/step):
//   - sC double-buffered; next step's C_t loaded during the B6 phase
//   - Amu (+ g_mp store) merged into the B2 phase (threads 0-31)
// Kg comes from Pt (rows of sigp) — load-bearing for stability.
// =====================================================================
__global__ void __launch_bounds__(256)
fwd_kernel(const float* __restrict__ a,
           float* __restrict__ out_mu, float* __restrict__ out_sig,
           const float* __restrict__ outA, const float* __restrict__ outC)
{
    __shared__ float sAbuf[2*1056];                 // ping-pong A (stride 33)
    __shared__ float sC2[2][256];                   // double-buffered C_t [8][32]
    __shared__ float sigp[1056];                    // sig_pred (stride 33)
    __shared__ __align__(16) float sigf[1024];      // sig_filt (stride 32)
    __shared__ float big[1024];                     // M1 | Pt | KgT | aug8
    __shared__ __align__(16) float T1b[32*36];      // T1 (stride 36)
    __shared__ float sAmu[ZD], serr[AD], smu[ZD];

    const int b = blockIdx.x, tid = threadIdx.x;
    const int i4 = tid >> 3;                // tiled-output row (0..31)
    const int jb = (tid & 7) << 2;          // tiled-output col block (x4)

    // ---- init: sig_pred = 20*I, mu = 0, load A_t[b][0], C_t[b][0] ----
    for (int e = tid; e < 1024; e += 256) {
        int i = e >> 5, j = e & 31;
        sigp[i*33 + j] = (i == j) ? 20.f : 0.f;
        sAbuf[i*33 + j] = outA[(size_t)(b*Tq)*1024 + e];
    }
    sC2[0][tid] = outC[(size_t)(b*Tq)*256 + tid];
    if (tid < ZD) smu[tid] = 0.f;
    __syncthreads();

    for (int t = 0; t < Tq; t++) {
        float* Ac  = sAbuf + (t & 1)*1056;
        float* Anx = sAbuf + ((t + 1) & 1)*1056;
        const float* sC  = sC2[t & 1];
        float*       sCn = sC2[(t + 1) & 1];
        const int btt = b*Tq + t;

        // B2 phase: M1 = C @ sigp ; Pt[l][j] = (sigp C^T)[j][l]
        //           + Amu = Ac @ mu (tid<32, extra work for warp 0)
        {
            int l = tid >> 5, j = tid & 31;
            float acc = 0.f;
            #pragma unroll
            for (int m = 0; m < 32; m++) acc += sC[l*32 + m]*sigp[m*33 + j];
            big[l*32 + j] = acc;
            float acc2 = 0.f;
            #pragma unroll
            for (int m = 0; m < 32; m++) acc2 += sigp[j*33 + m]*sC[l*32 + m];
            big[256 + l*32 + j] = acc2;
        }
        if (tid < ZD) {
            float acc = 0.f;
            #pragma unroll
            for (int m = 0; m < 32; m++) acc += Ac[tid*33 + m]*smu[m];
            sAmu[tid] = acc;
            if (t > 0) g_mp[(btt - 1)*ZD + tid] = acc;  // mu_pred[t] at slot t-1
        }
        __syncthreads();   // B2

        // B3 phase: S = M1 C^T + R -> [S|I] (tid<64) | err (tid 64..71)
        if (tid < 64) {
            int l = tid >> 3, n = tid & 7;
            float acc = 0.f;
            #pragma unroll
            for (int m = 0; m < 32; m++) acc += big[l*32 + m]*sC[n*32 + m];
            big[768 + l*16 + n]     = acc + ((l == n) ? 0.03f : 0.f);
            big[768 + l*16 + 8 + n] = (l == n) ? 1.f : 0.f;
        } else if (tid < 72) {
            int l = tid - 64;
            float acc = 0.f;
            #pragma unroll
            for (int m = 0; m < 32; m++) acc += sC[l*32 + m]*sAmu[m];
            serr[l] = a[(size_t)btt*AD + l] - acc;
        }
        __syncthreads();   // B3

        // B4 phase: invert 8x8 SPD (warp 0, Gauss-Jordan, verified)
        if (tid < 32) {
            int r = tid >> 2, c0 = (tid & 3)*4;
            #pragma unroll
            for (int p = 0; p < 8; p++) {
                float fc  = big[768 + r*16 + p];
                float p0 = big[768 + p*16 + c0];
                float p1 = big[768 + p*16 + c0 + 1];
                float p2 = big[768 + p*16 + c0 + 2];
                float p3 = big[768 + p*16 + c0 + 3];
                float pd = big[768 + p*16 + p];
                __syncwarp();
                float pinv = 1.f/pd;
                if (r == p) {
                    big[768 + r*16 + c0]     = p0*pinv;
                    big[768 + r*16 + c0 + 1] = p1*pinv;
                    big[768 + r*16 + c0 + 2] = p2*pinv;
                    big[768 + r*16 + c0 + 3] = p3*pinv;
                } else {
                    float f = fc*pinv;
                    big[768 + r*16 + c0]     -= f*p0;
                    big[768 + r*16 + c0 + 1] -= f*p1;
                    big[768 + r*16 + c0 + 2] -= f*p2;
                    big[768 + r*16 + c0 + 3] -= f*p3;
                }
                __syncwarp();
            }
        }
        __syncthreads();   // B4

        // B5 phase: Kg^T[l][i] = sum_n Pt[n][i] * Sinv[n][l]
        {
            int l = tid >> 5, i = tid & 31;
            float acc = 0.f;
            #pragma unroll
            for (int n = 0; n < 8; n++) acc += big[256 + n*32 + i]*big[768 + n*16 + 8 + l];
            big[512 + l*32 + i] = acc;
        }
        __syncthreads();   // B5

        // B6 phase: sig_f = sigp - Kg @ M1 (all) + prefetch A_{t+1}, C_{t+1}
        //           + mu_f = Amu + Kg @ err (tid<32)
        #pragma unroll
        for (int q = 0; q < 4; q++) {
            int e = tid + 256*q, i = e >> 5, j = e & 31;
            float v = sigp[i*33 + j];
            #pragma unroll
            for (int l = 0; l < 8; l++) v -= big[512 + l*32 + i]*big[l*32 + j];
            sigf[e] = v;
            g_sigf[(size_t)btt*1024 + e] = v;
            if (t == Tq - 1) out_sig[(size_t)btt*1024 + e] = v;
            if (t < Tq - 1)  Anx[i*33 + j] = outA[(size_t)(btt + 1)*1024 + e];
        }
        if (t < Tq - 1) sCn[tid] = outC[(size_t)(btt + 1)*256 + tid];
        if (tid < ZD) {
            float v = sAmu[tid];
            #pragma unroll
            for (int l = 0; l < 8; l++) v += big[512 + l*32 + tid]*serr[l];
            smu[tid] = v;
            g_muf[btt*ZD + tid] = v;
            if (t == Tq - 1) out_mu[btt*ZD + tid] = v;
        }
        __syncthreads();   // B6

        if (t < Tq - 1) {
            // B7 phase (tiled): T1[i4][jb..jb+3] = sum_m Anx[i4][m]*sigf[m][jb..+3]
            {
                float x0 = 0.f, x1 = 0.f, x2 = 0.f, x3 = 0.f;
                #pragma unroll
                for (int m = 0; m < 32; m++) {
                    float av = Anx[i4*33 + m];
                    const float4 s = *(const float4*)&sigf[m*32 + jb];
                    x0 += av*s.x; x1 += av*s.y; x2 += av*s.z; x3 += av*s.w;
                }
                T1b[i4*36 + jb]     = x0;
                T1b[i4*36 + jb + 1] = x1;
                T1b[i4*36 + jb + 2] = x2;
                T1b[i4*36 + jb + 3] = x3;
                float4 r = {x0, x1, x2, x3};
                *(float4*)(g_T1s + (size_t)btt*1024 + i4*32 + jb) = r;
            }
            __syncthreads();   // B7

            // B8 phase (tiled): sigp[i4][jb+s] = Q + sum_m T1[i4][m]*Anx[jb+s][m]
            {
                float a0 = (i4 == jb    ) ? 0.08f : 0.f;
                float a1 = (i4 == jb + 1) ? 0.08f : 0.f;
                float a2 = (i4 == jb + 2) ? 0.08f : 0.f;
                float a3 = (i4 == jb + 3) ? 0.08f : 0.f;
                #pragma unroll
                for (int m4 = 0; m4 < 32; m4 += 4) {
                    const float4 t4 = *(const float4*)&T1b[i4*36 + m4];
                    a0 += t4.x*Anx[(jb    )*33 + m4]     + t4.y*Anx[(jb    )*33 + m4 + 1]
                        + t4.z*Anx[(jb    )*33 + m4 + 2] + t4.w*Anx[(jb    )*33 + m4 + 3];
                    a1 += t4.x*Anx[(jb + 1)*33 + m4]     + t4.y*Anx[(jb + 1)*33 + m4 + 1]
                        + t4.z*Anx[(jb + 1)*33 + m4 + 2] + t4.w*Anx[(jb + 1)*33 + m4 + 3];
                    a2 += t4.x*Anx[(jb + 2)*33 + m4]     + t4.y*Anx[(jb + 2)*33 + m4 + 1]
                        + t4.z*Anx[(jb + 2)*33 + m4 + 2] + t4.w*Anx[(jb + 2)*33 + m4 + 3];
                    a3 += t4.x*Anx[(jb + 3)*33 + m4]     + t4.y*Anx[(jb + 3)*33 + m4 + 1]
                        + t4.z*Anx[(jb + 3)*33 + m4 + 2] + t4.w*Anx[(jb + 3)*33 + m4 + 3];
                }
                sigp[i4*33 + jb]     = a0;
                sigp[i4*33 + jb + 1] = a1;
                sigp[i4*33 + jb + 2] = a2;
                sigp[i4*33 + jb + 3] = a3;
                float4 r = {a0, a1, a2, a3};
                *(float4*)(g_sp + (size_t)btt*1024 + i4*32 + jb) = r;
            }
            __syncthreads();   // B8
        }
    }
}

// =====================================================================
// Kernel 4: batched solves X = sp^{-1} T1 (round-10 verified, unchanged).
// =====================================================================
__global__ void __launch_bounds__(256)
solve_kernel()
{
    const int lin = blockIdx.x;             // 0 .. Bq*(Tq-1)-1
    const int b = lin / (Tq - 1), t = lin % (Tq - 1);
    const size_t bt = (size_t)b*Tq + t;
    const int tid = threadIdx.x;
    const int c = tid >> 2, q = tid & 3;

    __shared__ float Tsh[32*33];
    __shared__ float sfac[2][32];
    __shared__ float spinv[2];

    // stage T1 coalesced -> shared (stride 33; STS conflict-free)
    #pragma unroll
    for (int k = 0; k < 4; k++) {
        int e = tid + 256*k, i = e >> 5, j = e & 31;
        Tsh[i*33 + j] = g_T1s[bt*1024 + e];
    }

    float reg[8];
    if (c < 32) {
        // sp symmetric: column c == row c (contiguous) -> 2 float4 loads
        const float4* bp = (const float4*)(g_sp + bt*1024 + c*32 + q*8);
        float4 r0 = bp[0], r1 = bp[1];
        reg[0] = r0.x; reg[1] = r0.y; reg[2] = r0.z; reg[3] = r0.w;
        reg[4] = r1.x; reg[5] = r1.y; reg[6] = r1.z; reg[7] = r1.w;
    }
    // pivot-0 prep: column 0 snapshot + reciprocal
    if (c == 0) {
        #pragma unroll
        for (int i = 0; i < 8; i++) sfac[0][q*8 + i] = reg[i];
        if (q == 0) spinv[0] = 1.f/reg[0];
    }
    __syncthreads();
    if (c >= 32) {
        // column (c-32) of T1 from padded shared (LDS conflict-free)
        #pragma unroll
        for (int i = 0; i < 8; i++) reg[i] = Tsh[(q*8 + i)*33 + (c - 32)];
    }

    #pragma unroll
    for (int p = 0; p < 32; p++) {
        const int pb = p & 1;
        const float piv = spinv[pb];
        float fac[8];
        #pragma unroll
        for (int i = 0; i < 8; i++) fac[i] = sfac[pb][q*8 + i];
        // row-p element of my column (pre-update), from the lane with q = p>>3
        float m_pc = __shfl_sync(0xffffffffu, reg[p & 7], p >> 3, 4);
        float mn = m_pc * piv;
        if (c > p) {
            #pragma unroll
            for (int i = 0; i < 8; i++) {
                int r = q*8 + i;
                reg[i] = (r == p) ? mn : (reg[i] - fac[i]*mn);
            }
            if (p < 31 && c == p + 1) {
                #pragma unroll
                for (int i = 0; i < 8; i++) sfac[pb ^ 1][q*8 + i] = reg[i];
                if (q == ((p + 1) >> 3)) spinv[pb ^ 1] = 1.f/reg[(p + 1) & 7];
            }
        }
        __syncthreads();
    }

    // stage X through shared (conflict-free STS), write coalesced
    if (c >= 32) {
        #pragma unroll
        for (int i = 0; i < 8; i++) Tsh[(q*8 + i)*33 + (c - 32)] = reg[i];
    }
    __syncthreads();
    #pragma unroll
    for (int k = 0; k < 4; k++) {
        int e = tid + 256*k, i = e >> 5, j = e & 31;
        g_X[bt*1024 + e] = Tsh[i*33 + j];
    }
}

// =====================================================================
// Kernel 5: RTS backward (verified, unchanged).
// =====================================================================
__global__ void __launch_bounds__(256)
bwd_kernel(float* __restrict__ out_mu, float* __restrict__ out_sig)
{
    __shared__ __align__(16) float X[1024], D[1024], G[1024], Ssn[1024];
    __shared__ float sdm[ZD], smf[ZD], sxv[ZD], smusn[ZD];

    const int b = blockIdx.x, tid = threadIdx.x;
    const int i4 = tid >> 3, jb = (tid & 7) << 2;

    {
        const size_t bt = (size_t)b*Tq + (Tq - 1);
        ((float4*)Ssn)[tid] = ((const float4*)(g_sigf + bt*1024))[tid];
        if (tid < ZD) smusn[tid] = g_muf[bt*ZD + tid];
    }
    __syncthreads();

    for (int t = Tq - 2; t >= 0; t--) {
        const size_t bt = (size_t)b*Tq + t;
        // pass0: loads
        ((float4*)X)[tid] = ((const float4*)(g_X + bt*1024))[tid];
        {
            float4 s = ((const float4*)Ssn)[tid];
            float4 p = ((const float4*)(g_sp + bt*1024))[tid];
            float4 d = {s.x - p.x, s.y - p.y, s.z - p.z, s.w - p.w};
            ((float4*)D)[tid] = d;
        }
        if (tid < ZD) {
            sdm[tid] = smusn[tid] - g_mp[bt*ZD + tid];
            smf[tid] = g_muf[bt*ZD + tid];
        }
        __syncthreads();

        // pass A: G = D @ X ; xv = X^T dm
        {
            float g0 = 0, g1 = 0, g2 = 0, g3 = 0;
            #pragma unroll
            for (int m = 0; m < 32; m++) {
                float dv = D[i4*32 + m];
                const float4 xm = *(const float4*)&X[m*32 + jb];
                g0 += dv*xm.x; g1 += dv*xm.y; g2 += dv*xm.z; g3 += dv*xm.w;
            }
            G[i4*32 + jb] = g0; G[i4*32 + jb + 1] = g1;
            G[i4*32 + jb + 2] = g2; G[i4*32 + jb + 3] = g3;
        }
        if (tid < ZD) {
            float v = 0.f;
            #pragma unroll
            for (int k = 0; k < 32; k++) v += X[k*32 + tid]*sdm[k];
            sxv[tid] = v;
        }
        __syncthreads();

        // pass B: sig_s = sf + X^T G ; mu_s = mf + xv
        {
            float4 acc = ((const float4*)(g_sigf + bt*1024))[tid];
            #pragma unroll
            for (int k = 0; k < 32; k++) {
                float xk = X[k*32 + i4];
                const float4 g4 = *(const float4*)&G[k*32 + jb];
                acc.x += xk*g4.x; acc.y += xk*g4.y; acc.z += xk*g4.z; acc.w += xk*g4.w;
            }
            ((float4*)(out_sig + bt*1024))[tid] = acc;
            ((float4*)Ssn)[tid] = acc;
        }
        if (tid < ZD) {
            float v = smf[tid] + sxv[tid];
            out_mu[bt*ZD + tid] = v;
            smusn[tid] = v;
        }
        __syncthreads();
    }
}

// =====================================================================
extern "C" void kernel_launch(void* const* d_in, const int* in_sizes, int n_in,
                              void* d_out, int out_size)
{
    const float* a       = (const float*)d_in[0];
    const float* a1      = (const float*)d_in[1];
    const float* W_ih    = (const float*)d_in[2];
    const float* W_hh    = (const float*)d_in[3];
    const float* b_ih    = (const float*)d_in[4];
    const float* b_hh    = (const float*)d_in[5];
    const float* W_alpha = (const float*)d_in[6];
    const float* b_alpha = (const float*)d_in[7];
    const float* Ag      = (const float*)d_in[8];
    const float* Cg      = (const float*)d_in[9];

    float* out    = (float*)d_out;
    float* out_mu = out;                              // [B,T,32]
    float* out_sg = out_mu + (size_t)BT*ZD;           // [B,T,32,32]
    float* out_A  = out_sg + (size_t)BT*ZD*ZD;        // [B,T,32,32]
    float* out_C  = out_A  + (size_t)BT*ZD*ZD;        // [B,T,8,32]

    lstm_kernel<<<Bq, 256>>>(a, a1, W_ih, W_hh, b_ih, b_hh, W_alpha, b_alpha);
    mix_kernel<<<BT/128, 256>>>(Ag, Cg, out_A, out_C);
    fwd_kernel<<<Bq, 256>>>(a, out_mu, out_sg, out_A, out_C);
    solve_kernel<<<Bq*(Tq - 1), 256>>>();
    bwd_kernel<<<Bq, 256>>>(out_mu, out_sg);
}

// round 13
// speedup vs baseline: 1.1884x; 1.0671x over previous
#include <cuda_runtime.h>

// ---------------- problem constants ----------------
#define Bq   256
#define Tq   128
#define AD   8
#define ZD   32
#define KM   16
#define HIDq 50
#define BT   (Bq*Tq)

// ---------------- device scratch ----------------
__device__ float g_w[BT*KM];
__device__ float g_sigf[(size_t)BT*1024];   // Sigma_f[t]
__device__ float g_T1s[(size_t)BT*1024];    // T1 = A_{t+1} Sigma_f[t]   (slot t, t<=T-2)
__device__ float g_sp[(size_t)BT*1024];     // Sigma_pred[t+1]           (slot t, t<=T-2)
__device__ float g_X[(size_t)BT*1024];      // X = sp^{-1} T1 (= J^T)    (slot t, t<=T-2)
__device__ float g_muf[BT*ZD];              // mu_f[t]
__device__ float g_mp[BT*ZD];               // mu_pred[t+1]              (slot t, t<=T-2)

// =====================================================================
// Kernel 1: LSTM over T + softmax mixture weights.
// Round-12 verified structure; W_hh row held in REGISTERS (tid<200),
// halving inner-loop LDS (1 broadcast per FMA). Same accumulation order.
// =====================================================================
__global__ void __launch_bounds__(256)
lstm_kernel(const float* __restrict__ a,  const float* __restrict__ a1,
            const float* __restrict__ W_ih, const float* __restrict__ W_hh,
            const float* __restrict__ b_ih, const float* __restrict__ b_hh,
            const float* __restrict__ W_alpha, const float* __restrict__ b_alpha)
{
    __shared__ float sWa[KM*HIDq];
    __shared__ float sh[HIDq], sc[HIDq], sx[AD], sg[200];

    const int b = blockIdx.x, tid = threadIdx.x;

    float wi[AD]; float bg = 0.f;
    float whh[HIDq];
    if (tid < 200) {
        #pragma unroll
        for (int j = 0; j < AD; j++) wi[j] = W_ih[tid*AD + j];
        bg = b_ih[tid] + b_hh[tid];
        #pragma unroll
        for (int j = 0; j < HIDq; j++) whh[j] = W_hh[tid*HIDq + j];
    }
    for (int i = tid; i < KM*HIDq; i += 256) sWa[i] = W_alpha[i];
    if (tid < HIDq) { sh[tid] = 0.f; sc[tid] = 0.f; }
    __syncthreads();

    for (int t = 0; t < Tq; t++) {
        if (tid < AD) sx[tid] = (t == 0) ? a1[tid] : a[(b*Tq + (t-1))*AD + tid];
        __syncthreads();                 // B1
        if (tid < 200) {
            float a0 = bg, a1_ = 0.f, a2 = 0.f, a3 = 0.f;
            #pragma unroll
            for (int j = 0; j < AD; j++) a0 += sx[j]*wi[j];
            #pragma unroll
            for (int j = 0; j < 48; j += 4) {
                a0  += sh[j  ]*whh[j  ];
                a1_ += sh[j+1]*whh[j+1];
                a2  += sh[j+2]*whh[j+2];
                a3  += sh[j+3]*whh[j+3];
            }
            a0  += sh[48]*whh[48];
            a1_ += sh[49]*whh[49];
            sg[tid] = (a0 + a1_) + (a2 + a3);
        }
        __syncthreads();                 // B2
        if (tid < HIDq) {
            float ig = 1.f/(1.f + __expf(-sg[tid]));
            float fg = 1.f/(1.f + __expf(-sg[HIDq + tid]));
            float gg = tanhf(sg[2*HIDq + tid]);
            float og = 1.f/(1.f + __expf(-sg[3*HIDq + tid]));
            float c  = fg*sc[tid] + ig*gg;
            sc[tid] = c;
            sh[tid] = og*tanhf(c);
        }
        __syncthreads();                 // B3
        if (tid < 32) {
            float logit = -1e30f;
            if (tid < KM) {
                logit = b_alpha[tid];
                #pragma unroll
                for (int j = 0; j < HIDq; j++) logit += sh[j]*sWa[tid*HIDq + j];
            }
            float m = logit;
            #pragma unroll
            for (int d = 8; d; d >>= 1)
                m = fmaxf(m, __shfl_xor_sync(0xffffffffu, m, d, 16));
            float e = __expf(logit - m);
            float s = e;
            #pragma unroll
            for (int d = 8; d; d >>= 1)
                s += __shfl_xor_sync(0xffffffffu, s, d, 16);
            if (tid < KM) g_w[(b*Tq + t)*KM + tid] = e/s;
        }
    }
}

// =====================================================================
// Kernel 2: A_t/C_t mixing (verified, unchanged).
// =====================================================================
__global__ void __launch_bounds__(256)
mix_kernel(const float* __restrict__ Ag, const float* __restrict__ Cg,
           float* __restrict__ outA, float* __restrict__ outC)
{
    __shared__ float sw[128*KM];
    const int tid = threadIdx.x;
    const int r0  = blockIdx.x * 128;
    for (int i = tid; i < 128*KM; i += 256) sw[i] = g_w[r0*KM + i];
    __syncthreads();

    for (int c = tid; c < 1280; c += 256) {
        float av[KM];
        if (c < 1024) {
            #pragma unroll
            for (int k = 0; k < KM; k++) av[k] = Ag[k*1024 + c];
            for (int r = 0; r < 128; r++) {
                float acc = 0.f;
                #pragma unroll
                for (int k = 0; k < KM; k++) acc += sw[r*KM + k]*av[k];
                outA[(size_t)(r0 + r)*1024 + c] = acc;
            }
        } else {
            const int cc = c - 1024;
            #pragma unroll
            for (int k = 0; k < KM; k++) av[k] = Cg[k*256 + cc];
            for (int r = 0; r < 128; r++) {
                float acc = 0.f;
                #pragma unroll
                for (int k = 0; k < KM; k++) acc += sw[r*KM + k]*av[k];
                outC[(r0 + r)*256 + cc] = acc;
            }
        }
    }
}

// =====================================================================
// Kernel 3: Kalman forward filter (round-12 verified, unchanged).
// 7 barriers/step; Kg from Pt (load-bearing for stability).
// =====================================================================
__global__ void __launch_bounds__(256)
fwd_kernel(const float* __restrict__ a,
           float* __restrict__ out_mu, float* __restrict__ out_sig,
           const float* __restrict__ outA, const float* __restrict__ outC)
{
    __shared__ float sAbuf[2*1056];                 // ping-pong A (stride 33)
    __shared__ float sC2[2][256];                   // double-buffered C_t [8][32]
    __shared__ float sigp[1056];                    // sig_pred (stride 33)
    __shared__ __align__(16) float sigf[1024];      // sig_filt (stride 32)
    __shared__ float big[1024];                     // M1 | Pt | KgT | aug8
    __shared__ __align__(16) float T1b[32*36];      // T1 (stride 36)
    __shared__ float sAmu[ZD], serr[AD], smu[ZD];

    const int b = blockIdx.x, tid = threadIdx.x;
    const int i4 = tid >> 3;                // tiled-output row (0..31)
    const int jb = (tid & 7) << 2;          // tiled-output col block (x4)

    // ---- init: sig_pred = 20*I, mu = 0, load A_t[b][0], C_t[b][0] ----
    for (int e = tid; e < 1024; e += 256) {
        int i = e >> 5, j = e & 31;
        sigp[i*33 + j] = (i == j) ? 20.f : 0.f;
        sAbuf[i*33 + j] = outA[(size_t)(b*Tq)*1024 + e];
    }
    sC2[0][tid] = outC[(size_t)(b*Tq)*256 + tid];
    if (tid < ZD) smu[tid] = 0.f;
    __syncthreads();

    for (int t = 0; t < Tq; t++) {
        float* Ac  = sAbuf + (t & 1)*1056;
        float* Anx = sAbuf + ((t + 1) & 1)*1056;
        const float* sC  = sC2[t & 1];
        float*       sCn = sC2[(t + 1) & 1];
        const int btt = b*Tq + t;

        // B2 phase: M1 = C @ sigp ; Pt[l][j] = (sigp C^T)[j][l]
        //           + Amu = Ac @ mu (tid<32, extra work for warp 0)
        {
            int l = tid >> 5, j = tid & 31;
            float acc = 0.f;
            #pragma unroll
            for (int m = 0; m < 32; m++) acc += sC[l*32 + m]*sigp[m*33 + j];
            big[l*32 + j] = acc;
            float acc2 = 0.f;
            #pragma unroll
            for (int m = 0; m < 32; m++) acc2 += sigp[j*33 + m]*sC[l*32 + m];
            big[256 + l*32 + j] = acc2;
        }
        if (tid < ZD) {
            float acc = 0.f;
            #pragma unroll
            for (int m = 0; m < 32; m++) acc += Ac[tid*33 + m]*smu[m];
            sAmu[tid] = acc;
            if (t > 0) g_mp[(btt - 1)*ZD + tid] = acc;  // mu_pred[t] at slot t-1
        }
        __syncthreads();   // B2

        // B3 phase: S = M1 C^T + R -> [S|I] (tid<64) | err (tid 64..71)
        if (tid < 64) {
            int l = tid >> 3, n = tid & 7;
            float acc = 0.f;
            #pragma unroll
            for (int m = 0; m < 32; m++) acc += big[l*32 + m]*sC[n*32 + m];
            big[768 + l*16 + n]     = acc + ((l == n) ? 0.03f : 0.f);
            big[768 + l*16 + 8 + n] = (l == n) ? 1.f : 0.f;
        } else if (tid < 72) {
            int l = tid - 64;
            float acc = 0.f;
            #pragma unroll
            for (int m = 0; m < 32; m++) acc += sC[l*32 + m]*sAmu[m];
            serr[l] = a[(size_t)btt*AD + l] - acc;
        }
        __syncthreads();   // B3

        // B4 phase: invert 8x8 SPD (warp 0, Gauss-Jordan, verified)
        if (tid < 32) {
            int r = tid >> 2, c0 = (tid & 3)*4;
            #pragma unroll
            for (int p = 0; p < 8; p++) {
                float fc  = big[768 + r*16 + p];
                float p0 = big[768 + p*16 + c0];
                float p1 = big[768 + p*16 + c0 + 1];
                float p2 = big[768 + p*16 + c0 + 2];
                float p3 = big[768 + p*16 + c0 + 3];
                float pd = big[768 + p*16 + p];
                __syncwarp();
                float pinv = 1.f/pd;
                if (r == p) {
                    big[768 + r*16 + c0]     = p0*pinv;
                    big[768 + r*16 + c0 + 1] = p1*pinv;
                    big[768 + r*16 + c0 + 2] = p2*pinv;
                    big[768 + r*16 + c0 + 3] = p3*pinv;
                } else {
                    float f = fc*pinv;
                    big[768 + r*16 + c0]     -= f*p0;
                    big[768 + r*16 + c0 + 1] -= f*p1;
                    big[768 + r*16 + c0 + 2] -= f*p2;
                    big[768 + r*16 + c0 + 3] -= f*p3;
                }
                __syncwarp();
            }
        }
        __syncthreads();   // B4

        // B5 phase: Kg^T[l][i] = sum_n Pt[n][i] * Sinv[n][l]
        {
            int l = tid >> 5, i = tid & 31;
            float acc = 0.f;
            #pragma unroll
            for (int n = 0; n < 8; n++) acc += big[256 + n*32 + i]*big[768 + n*16 + 8 + l];
            big[512 + l*32 + i] = acc;
        }
        __syncthreads();   // B5

        // B6 phase: sig_f = sigp - Kg @ M1 (all) + prefetch A_{t+1}, C_{t+1}
        //           + mu_f = Amu + Kg @ err (tid<32)
        #pragma unroll
        for (int q = 0; q < 4; q++) {
            int e = tid + 256*q, i = e >> 5, j = e & 31;
            float v = sigp[i*33 + j];
            #pragma unroll
            for (int l = 0; l < 8; l++) v -= big[512 + l*32 + i]*big[l*32 + j];
            sigf[e] = v;
            g_sigf[(size_t)btt*1024 + e] = v;
            if (t == Tq - 1) out_sig[(size_t)btt*1024 + e] = v;
            if (t < Tq - 1)  Anx[i*33 + j] = outA[(size_t)(btt + 1)*1024 + e];
        }
        if (t < Tq - 1) sCn[tid] = outC[(size_t)(btt + 1)*256 + tid];
        if (tid < ZD) {
            float v = sAmu[tid];
            #pragma unroll
            for (int l = 0; l < 8; l++) v += big[512 + l*32 + tid]*serr[l];
            smu[tid] = v;
            g_muf[btt*ZD + tid] = v;
            if (t == Tq - 1) out_mu[btt*ZD + tid] = v;
        }
        __syncthreads();   // B6

        if (t < Tq - 1) {
            // B7 phase (tiled): T1[i4][jb..jb+3] = sum_m Anx[i4][m]*sigf[m][jb..+3]
            {
                float x0 = 0.f, x1 = 0.f, x2 = 0.f, x3 = 0.f;
                #pragma unroll
                for (int m = 0; m < 32; m++) {
                    float av = Anx[i4*33 + m];
                    const float4 s = *(const float4*)&sigf[m*32 + jb];
                    x0 += av*s.x; x1 += av*s.y; x2 += av*s.z; x3 += av*s.w;
                }
                T1b[i4*36 + jb]     = x0;
                T1b[i4*36 + jb + 1] = x1;
                T1b[i4*36 + jb + 2] = x2;
                T1b[i4*36 + jb + 3] = x3;
                float4 r = {x0, x1, x2, x3};
                *(float4*)(g_T1s + (size_t)btt*1024 + i4*32 + jb) = r;
            }
            __syncthreads();   // B7

            // B8 phase (tiled): sigp[i4][jb+s] = Q + sum_m T1[i4][m]*Anx[jb+s][m]
            {
                float a0 = (i4 == jb    ) ? 0.08f : 0.f;
                float a1 = (i4 == jb + 1) ? 0.08f : 0.f;
                float a2 = (i4 == jb + 2) ? 0.08f : 0.f;
                float a3 = (i4 == jb + 3) ? 0.08f : 0.f;
                #pragma unroll
                for (int m4 = 0; m4 < 32; m4 += 4) {
                    const float4 t4 = *(const float4*)&T1b[i4*36 + m4];
                    a0 += t4.x*Anx[(jb    )*33 + m4]     + t4.y*Anx[(jb    )*33 + m4 + 1]
                        + t4.z*Anx[(jb    )*33 + m4 + 2] + t4.w*Anx[(jb    )*33 + m4 + 3];
                    a1 += t4.x*Anx[(jb + 1)*33 + m4]     + t4.y*Anx[(jb + 1)*33 + m4 + 1]
                        + t4.z*Anx[(jb + 1)*33 + m4 + 2] + t4.w*Anx[(jb + 1)*33 + m4 + 3];
                    a2 += t4.x*Anx[(jb + 2)*33 + m4]     + t4.y*Anx[(jb + 2)*33 + m4 + 1]
                        + t4.z*Anx[(jb + 2)*33 + m4 + 2] + t4.w*Anx[(jb + 2)*33 + m4 + 3];
                    a3 += t4.x*Anx[(jb + 3)*33 + m4]     + t4.y*Anx[(jb + 3)*33 + m4 + 1]
                        + t4.z*Anx[(jb + 3)*33 + m4 + 2] + t4.w*Anx[(jb + 3)*33 + m4 + 3];
                }
                sigp[i4*33 + jb]     = a0;
                sigp[i4*33 + jb + 1] = a1;
                sigp[i4*33 + jb + 2] = a2;
                sigp[i4*33 + jb + 3] = a3;
                float4 r = {a0, a1, a2, a3};
                *(float4*)(g_sp + (size_t)btt*1024 + i4*32 + jb) = r;
            }
            __syncthreads();   // B8
        }
    }
}

// =====================================================================
// Kernel 4: batched solves X = sp^{-1} T1 (round-10 verified, unchanged).
// =====================================================================
__global__ void __launch_bounds__(256)
solve_kernel()
{
    const int lin = blockIdx.x;             // 0 .. Bq*(Tq-1)-1
    const int b = lin / (Tq - 1), t = lin % (Tq - 1);
    const size_t bt = (size_t)b*Tq + t;
    const int tid = threadIdx.x;
    const int c = tid >> 2, q = tid & 3;

    __shared__ float Tsh[32*33];
    __shared__ float sfac[2][32];
    __shared__ float spinv[2];

    // stage T1 coalesced -> shared (stride 33; STS conflict-free)
    #pragma unroll
    for (int k = 0; k < 4; k++) {
        int e = tid + 256*k, i = e >> 5, j = e & 31;
        Tsh[i*33 + j] = g_T1s[bt*1024 + e];
    }

    float reg[8];
    if (c < 32) {
        // sp symmetric: column c == row c (contiguous) -> 2 float4 loads
        const float4* bp = (const float4*)(g_sp + bt*1024 + c*32 + q*8);
        float4 r0 = bp[0], r1 = bp[1];
        reg[0] = r0.x; reg[1] = r0.y; reg[2] = r0.z; reg[3] = r0.w;
        reg[4] = r1.x; reg[5] = r1.y; reg[6] = r1.z; reg[7] = r1.w;
    }
    // pivot-0 prep: column 0 snapshot + reciprocal
    if (c == 0) {
        #pragma unroll
        for (int i = 0; i < 8; i++) sfac[0][q*8 + i] = reg[i];
        if (q == 0) spinv[0] = 1.f/reg[0];
    }
    __syncthreads();
    if (c >= 32) {
        // column (c-32) of T1 from padded shared (LDS conflict-free)
        #pragma unroll
        for (int i = 0; i < 8; i++) reg[i] = Tsh[(q*8 + i)*33 + (c - 32)];
    }

    #pragma unroll
    for (int p = 0; p < 32; p++) {
        const int pb = p & 1;
        const float piv = spinv[pb];
        float fac[8];
        #pragma unroll
        for (int i = 0; i < 8; i++) fac[i] = sfac[pb][q*8 + i];
        // row-p element of my column (pre-update), from the lane with q = p>>3
        float m_pc = __shfl_sync(0xffffffffu, reg[p & 7], p >> 3, 4);
        float mn = m_pc * piv;
        if (c > p) {
            #pragma unroll
            for (int i = 0; i < 8; i++) {
                int r = q*8 + i;
                reg[i] = (r == p) ? mn : (reg[i] - fac[i]*mn);
            }
            if (p < 31 && c == p + 1) {
                #pragma unroll
                for (int i = 0; i < 8; i++) sfac[pb ^ 1][q*8 + i] = reg[i];
                if (q == ((p + 1) >> 3)) spinv[pb ^ 1] = 1.f/reg[(p + 1) & 7];
            }
        }
        __syncthreads();
    }

    // stage X through shared (conflict-free STS), write coalesced
    if (c >= 32) {
        #pragma unroll
        for (int i = 0; i < 8; i++) Tsh[(q*8 + i)*33 + (c - 32)] = reg[i];
    }
    __syncthreads();
    #pragma unroll
    for (int k = 0; k < 4; k++) {
        int e = tid + 256*k, i = e >> 5, j = e & 31;
        g_X[bt*1024 + e] = Tsh[i*33 + j];
    }
}

// =====================================================================
// Kernel 5: RTS backward — round-12 verified math with a REGISTER
// PREFETCH pipeline: X/sp/sigf/mp/muf for step t-1 are loaded into
// registers during step t's pass A (they depend on NO backward state),
// so pass0 is STS+FSUB only and pass B's accumulator init is a register.
// Same 3 barriers/step, identical arithmetic.
// =====================================================================
__global__ void __launch_bounds__(256)
bwd_kernel(float* __restrict__ out_mu, float* __restrict__ out_sig)
{
    __shared__ __align__(16) float X[1024], D[1024], G[1024], Ssn[1024];
    __shared__ float sdm[ZD], smf[ZD], sxv[ZD], smusn[ZD];

    const int b = blockIdx.x, tid = threadIdx.x;
    const int i4 = tid >> 3, jb = (tid & 7) << 2;

    float4 rX, rSp, rSf;       // prefetched values for the CURRENT step
    float  rmp = 0.f, rmf = 0.f;

    {
        const size_t btl = (size_t)b*Tq + (Tq - 1);
        ((float4*)Ssn)[tid] = ((const float4*)(g_sigf + btl*1024))[tid];
        if (tid < ZD) smusn[tid] = g_muf[btl*ZD + tid];
        // prefetch for t = Tq-2
        const size_t bt0 = (size_t)b*Tq + (Tq - 2);
        rX  = ((const float4*)(g_X    + bt0*1024))[tid];
        rSp = ((const float4*)(g_sp   + bt0*1024))[tid];
        rSf = ((const float4*)(g_sigf + bt0*1024))[tid];
        if (tid < ZD) { rmp = g_mp[bt0*ZD + tid]; rmf = g_muf[bt0*ZD + tid]; }
    }
    __syncthreads();

    for (int t = Tq - 2; t >= 0; t--) {
        const size_t bt = (size_t)b*Tq + t;
        // pass0: shared stores from prefetched registers (no global latency)
        ((float4*)X)[tid] = rX;
        {
            float4 s = ((const float4*)Ssn)[tid];
            float4 d = {s.x - rSp.x, s.y - rSp.y, s.z - rSp.z, s.w - rSp.w};
            ((float4*)D)[tid] = d;
        }
        if (tid < ZD) {
            sdm[tid] = smusn[tid] - rmp;
            smf[tid] = rmf;
        }
        __syncthreads();

        // pass A: issue next prefetch FIRST (overlaps compute), then G, xv
        float4 nX, nSp, nSf; float nmp = 0.f, nmf = 0.f;
        if (t > 0) {
            const size_t btn = bt - 1;
            nX  = ((const float4*)(g_X    + btn*1024))[tid];
            nSp = ((const float4*)(g_sp   + btn*1024))[tid];
            nSf = ((const float4*)(g_sigf + btn*1024))[tid];
            if (tid < ZD) { nmp = g_mp[btn*ZD + tid]; nmf = g_muf[btn*ZD + tid]; }
        }
        {
            float g0 = 0, g1 = 0, g2 = 0, g3 = 0;
            #pragma unroll
            for (int m = 0; m < 32; m++) {
                float dv = D[i4*32 + m];
                const float4 xm = *(const float4*)&X[m*32 + jb];
                g0 += dv*xm.x; g1 += dv*xm.y; g2 += dv*xm.z; g3 += dv*xm.w;
            }
            G[i4*32 + jb] = g0; G[i4*32 + jb + 1] = g1;
            G[i4*32 + jb + 2] = g2; G[i4*32 + jb + 3] = g3;
        }
        if (tid < ZD) {
            float v = 0.f;
            #pragma unroll
            for (int k = 0; k < 32; k++) v += X[k*32 + tid]*sdm[k];
            sxv[tid] = v;
        }
        __syncthreads();

        // pass B: sig_s = rSf + X^T G ; mu_s = mf + xv
        {
            float4 acc = rSf;
            #pragma unroll
            for (int k = 0; k < 32; k++) {
                float xk = X[k*32 + i4];
                const float4 g4 = *(const float4*)&G[k*32 + jb];
                acc.x += xk*g4.x; acc.y += xk*g4.y; acc.z += xk*g4.z; acc.w += xk*g4.w;
            }
            ((float4*)(out_sig + bt*1024))[tid] = acc;
            ((float4*)Ssn)[tid] = acc;
        }
        if (tid < ZD) {
            float v = smf[tid] + sxv[tid];
            out_mu[bt*ZD + tid] = v;
            smusn[tid] = v;
        }
        __syncthreads();

        rX = nX; rSp = nSp; rSf = nSf; rmp = nmp; rmf = nmf;
    }
}

// =====================================================================
extern "C" void kernel_launch(void* const* d_in, const int* in_sizes, int n_in,
                              void* d_out, int out_size)
{
    const float* a       = (const float*)d_in[0];
    const float* a1      = (const float*)d_in[1];
    const float* W_ih    = (const float*)d_in[2];
    const float* W_hh    = (const float*)d_in[3];
    const float* b_ih    = (const float*)d_in[4];
    const float* b_hh    = (const float*)d_in[5];
    const float* W_alpha = (const float*)d_in[6];
    const float* b_alpha = (const float*)d_in[7];
    const float* Ag      = (const float*)d_in[8];
    const float* Cg      = (const float*)d_in[9];

    float* out    = (float*)d_out;
    float* out_mu = out;                              // [B,T,32]
    float* out_sg = out_mu + (size_t)BT*ZD;           // [B,T,32,32]
    float* out_A  = out_sg + (size_t)BT*ZD*ZD;        // [B,T,32,32]
    float* out_C  = out_A  + (size_t)BT*ZD*ZD;        // [B,T,8,32]

    lstm_kernel<<<Bq, 256>>>(a, a1, W_ih, W_hh, b_ih, b_hh, W_alpha, b_alpha);
    mix_kernel<<<BT/128, 256>>>(Ag, Cg, out_A, out_C);
    fwd_kernel<<<Bq, 256>>>(a, out_mu, out_sg, out_A, out_C);
    solve_kernel<<<Bq*(Tq - 1), 256>>>();
    bwd_kernel<<<Bq, 256>>>(out_mu, out_sg);
}

// round 14
// speedup vs baseline: 1.2246x; 1.0305x over previous
#include <cuda_runtime.h>

// ---------------- problem constants ----------------
#define Bq   256
#define Tq   128
#define AD   8
#define ZD   32
#define KM   16
#define HIDq 50
#define BT   (Bq*Tq)

// ---------------- device scratch ----------------
__device__ float g_w[BT*KM];
__device__ float g_sigf[(size_t)BT*1024];   // Sigma_f[t]
__device__ float g_T1s[(size_t)BT*1024];    // T1 = A_{t+1} Sigma_f[t]   (slot t, t<=T-2)
__device__ float g_sp[(size_t)BT*1024];     // Sigma_pred[t+1]           (slot t, t<=T-2)
__device__ float g_X[(size_t)BT*1024];      // X = sp^{-1} T1 (= J^T)    (slot t, t<=T-2)
__device__ float g_muf[BT*ZD];              // mu_f[t]
__device__ float g_mp[BT*ZD];               // mu_pred[t+1]              (slot t, t<=T-2)

// =====================================================================
// Kernel 1: LSTM over T + softmax mixture weights.
// Round-13 verified body; sx double-buffered (prefetched by tid 200-207
// during the gates phase) -> 2 barriers/step.
// =====================================================================
__global__ void __launch_bounds__(256)
lstm_kernel(const float* __restrict__ a,  const float* __restrict__ a1,
            const float* __restrict__ W_ih, const float* __restrict__ W_hh,
            const float* __restrict__ b_ih, const float* __restrict__ b_hh,
            const float* __restrict__ W_alpha, const float* __restrict__ b_alpha)
{
    __shared__ float sWa[KM*HIDq];
    __shared__ float sh[HIDq], sc[HIDq], sx[2][AD], sg[200];

    const int b = blockIdx.x, tid = threadIdx.x;

    float wi[AD]; float bg = 0.f;
    float whh[HIDq];
    if (tid < 200) {
        #pragma unroll
        for (int j = 0; j < AD; j++) wi[j] = W_ih[tid*AD + j];
        bg = b_ih[tid] + b_hh[tid];
        #pragma unroll
        for (int j = 0; j < HIDq; j++) whh[j] = W_hh[tid*HIDq + j];
    }
    for (int i = tid; i < KM*HIDq; i += 256) sWa[i] = W_alpha[i];
    if (tid < HIDq) { sh[tid] = 0.f; sc[tid] = 0.f; }
    if (tid < AD)   sx[0][tid] = a1[tid];
    __syncthreads();

    for (int t = 0; t < Tq; t++) {
        const float* x = sx[t & 1];
        if (tid < 200) {
            float a0 = bg, a1_ = 0.f, a2 = 0.f, a3 = 0.f;
            #pragma unroll
            for (int j = 0; j < AD; j++) a0 += x[j]*wi[j];
            #pragma unroll
            for (int j = 0; j < 48; j += 4) {
                a0  += sh[j  ]*whh[j  ];
                a1_ += sh[j+1]*whh[j+1];
                a2  += sh[j+2]*whh[j+2];
                a3  += sh[j+3]*whh[j+3];
            }
            a0  += sh[48]*whh[48];
            a1_ += sh[49]*whh[49];
            sg[tid] = (a0 + a1_) + (a2 + a3);
        } else if (tid < 208 && t < Tq - 1) {
            // prefetch next input: joint[t+1] = a[t]
            sx[(t + 1) & 1][tid - 200] = a[(b*Tq + t)*AD + (tid - 200)];
        }
        __syncthreads();                 // B2
        if (tid < HIDq) {
            float ig = 1.f/(1.f + __expf(-sg[tid]));
            float fg = 1.f/(1.f + __expf(-sg[HIDq + tid]));
            float gg = tanhf(sg[2*HIDq + tid]);
            float og = 1.f/(1.f + __expf(-sg[3*HIDq + tid]));
            float c  = fg*sc[tid] + ig*gg;
            sc[tid] = c;
            sh[tid] = og*tanhf(c);
        }
        __syncthreads();                 // B3
        if (tid < 32) {
            float logit = -1e30f;
            if (tid < KM) {
                logit = b_alpha[tid];
                #pragma unroll
                for (int j = 0; j < HIDq; j++) logit += sh[j]*sWa[tid*HIDq + j];
            }
            float m = logit;
            #pragma unroll
            for (int d = 8; d; d >>= 1)
                m = fmaxf(m, __shfl_xor_sync(0xffffffffu, m, d, 16));
            float e = __expf(logit - m);
            float s = e;
            #pragma unroll
            for (int d = 8; d; d >>= 1)
                s += __shfl_xor_sync(0xffffffffu, s, d, 16);
            if (tid < KM) g_w[(b*Tq + t)*KM + tid] = e/s;
        }
    }
}

// =====================================================================
// Kernel 2: A_t/C_t mixing (verified, unchanged).
// =====================================================================
__global__ void __launch_bounds__(256)
mix_kernel(const float* __restrict__ Ag, const float* __restrict__ Cg,
           float* __restrict__ outA, float* __restrict__ outC)
{
    __shared__ float sw[128*KM];
    const int tid = threadIdx.x;
    const int r0  = blockIdx.x * 128;
    for (int i = tid; i < 128*KM; i += 256) sw[i] = g_w[r0*KM + i];
    __syncthreads();

    for (int c = tid; c < 1280; c += 256) {
        float av[KM];
        if (c < 1024) {
            #pragma unroll
            for (int k = 0; k < KM; k++) av[k] = Ag[k*1024 + c];
            for (int r = 0; r < 128; r++) {
                float acc = 0.f;
                #pragma unroll
                for (int k = 0; k < KM; k++) acc += sw[r*KM + k]*av[k];
                outA[(size_t)(r0 + r)*1024 + c] = acc;
            }
        } else {
            const int cc = c - 1024;
            #pragma unroll
            for (int k = 0; k < KM; k++) av[k] = Cg[k*256 + cc];
            for (int r = 0; r < 128; r++) {
                float acc = 0.f;
                #pragma unroll
                for (int k = 0; k < KM; k++) acc += sw[r*KM + k]*av[k];
                outC[(r0 + r)*256 + cc] = acc;
            }
        }
    }
}

// =====================================================================
// Kernel 3: Kalman forward filter — round-13 verified math, 5 barrier
// phases/step:
//   B2 : M1/Pt (all) + Amu (tid<32)
//   B34: warp0 computes S (bitwise-identical order) + syncwarp + invert;
//        warp2 computes err
//   B6 : tiled (i4,jb): local kg (identical n-order) + sigf + prefetch
//        A_{t+1}/C_{t+1} + mu_f (tid<32, local kg)
//   B7 : T1     B8 : sigp
// Kg from Pt (rows of sigp) — load-bearing for stability.
// =====================================================================
__global__ void __launch_bounds__(256)
fwd_kernel(const float* __restrict__ a,
           float* __restrict__ out_mu, float* __restrict__ out_sig,
           const float* __restrict__ outA, const float* __restrict__ outC)
{
    __shared__ float sAbuf[2*1056];                 // ping-pong A (stride 33)
    __shared__ float sC2[2][256];                   // double-buffered C_t [8][32]
    __shared__ float sigp[1056];                    // sig_pred (stride 33)
    __shared__ __align__(16) float sigf[1024];      // sig_filt (stride 32)
    __shared__ __align__(16) float big[1024];       // M1 | Pt | (unused) | aug8
    __shared__ __align__(16) float T1b[32*36];      // T1 (stride 36)
    __shared__ float sAmu[ZD], serr[AD], smu[ZD];

    const int b = blockIdx.x, tid = threadIdx.x;
    const int i4 = tid >> 3;                // tiled-output row (0..31)
    const int jb = (tid & 7) << 2;          // tiled-output col block (x4)

    // ---- init: sig_pred = 20*I, mu = 0, load A_t[b][0], C_t[b][0] ----
    for (int e = tid; e < 1024; e += 256) {
        int i = e >> 5, j = e & 31;
        sigp[i*33 + j] = (i == j) ? 20.f : 0.f;
        sAbuf[i*33 + j] = outA[(size_t)(b*Tq)*1024 + e];
    }
    sC2[0][tid] = outC[(size_t)(b*Tq)*256 + tid];
    if (tid < ZD) smu[tid] = 0.f;
    __syncthreads();

    for (int t = 0; t < Tq; t++) {
        float* Ac  = sAbuf + (t & 1)*1056;
        float* Anx = sAbuf + ((t + 1) & 1)*1056;
        const float* sC  = sC2[t & 1];
        float*       sCn = sC2[(t + 1) & 1];
        const int btt = b*Tq + t;

        // B2 phase: M1 = C @ sigp ; Pt[l][j] = (sigp C^T)[j][l]
        //           + Amu = Ac @ mu (tid<32)
        {
            int l = tid >> 5, j = tid & 31;
            float acc = 0.f;
            #pragma unroll
            for (int m = 0; m < 32; m++) acc += sC[l*32 + m]*sigp[m*33 + j];
            big[l*32 + j] = acc;
            float acc2 = 0.f;
            #pragma unroll
            for (int m = 0; m < 32; m++) acc2 += sigp[j*33 + m]*sC[l*32 + m];
            big[256 + l*32 + j] = acc2;
        }
        if (tid < ZD) {
            float acc = 0.f;
            #pragma unroll
            for (int m = 0; m < 32; m++) acc += Ac[tid*33 + m]*smu[m];
            sAmu[tid] = acc;
            if (t > 0) g_mp[(btt - 1)*ZD + tid] = acc;  // mu_pred[t] at slot t-1
        }
        __syncthreads();   // B2

        // B34 phase: warp0 = S aug (2 outputs/lane, same m-order) then invert;
        //            warp2 (tid 64..71) = err
        if (tid < 32) {
            #pragma unroll
            for (int h = 0; h < 2; h++) {
                int o = tid + 32*h;
                int l = o >> 3, n = o & 7;
                float acc = 0.f;
                #pragma unroll
                for (int m = 0; m < 32; m++) acc += big[l*32 + m]*sC[n*32 + m];
                big[768 + l*16 + n]     = acc + ((l == n) ? 0.03f : 0.f);
                big[768 + l*16 + 8 + n] = (l == n) ? 1.f : 0.f;
            }
            __syncwarp();
            // invert 8x8 SPD (Gauss-Jordan, verified)
            int r = tid >> 2, c0 = (tid & 3)*4;
            #pragma unroll
            for (int p = 0; p < 8; p++) {
                float fc  = big[768 + r*16 + p];
                float p0 = big[768 + p*16 + c0];
                float p1 = big[768 + p*16 + c0 + 1];
                float p2 = big[768 + p*16 + c0 + 2];
                float p3 = big[768 + p*16 + c0 + 3];
                float pd = big[768 + p*16 + p];
                __syncwarp();
                float pinv = 1.f/pd;
                if (r == p) {
                    big[768 + r*16 + c0]     = p0*pinv;
                    big[768 + r*16 + c0 + 1] = p1*pinv;
                    big[768 + r*16 + c0 + 2] = p2*pinv;
                    big[768 + r*16 + c0 + 3] = p3*pinv;
                } else {
                    float f = fc*pinv;
                    big[768 + r*16 + c0]     -= f*p0;
                    big[768 + r*16 + c0 + 1] -= f*p1;
                    big[768 + r*16 + c0 + 2] -= f*p2;
                    big[768 + r*16 + c0 + 3] -= f*p3;
                }
                __syncwarp();
            }
        } else if (tid >= 64 && tid < 72) {
            int l = tid - 64;
            float acc = 0.f;
            #pragma unroll
            for (int m = 0; m < 32; m++) acc += sC[l*32 + m]*sAmu[m];
            serr[l] = a[(size_t)btt*AD + l] - acc;
        }
        __syncthreads();   // B34

        // B6 phase (tiled): local kg; sigf row i4 cols jb..jb+3;
        // prefetch A_{t+1}, C_{t+1}; mu_f (tid<32, local kg, same order)
        {
            float kg[8];
            #pragma unroll
            for (int l = 0; l < 8; l++) {
                float acc = 0.f;
                #pragma unroll
                for (int n = 0; n < 8; n++)
                    acc += big[256 + n*32 + i4]*big[768 + n*16 + 8 + l];
                kg[l] = acc;
            }
            float4 v = {sigp[i4*33 + jb],     sigp[i4*33 + jb + 1],
                        sigp[i4*33 + jb + 2], sigp[i4*33 + jb + 3]};
            #pragma unroll
            for (int l = 0; l < 8; l++) {
                float k = kg[l];
                const float4 m = *(const float4*)&big[l*32 + jb];
                v.x -= k*m.x; v.y -= k*m.y; v.z -= k*m.z; v.w -= k*m.w;
            }
            *(float4*)&sigf[i4*32 + jb] = v;
            *(float4*)(g_sigf + (size_t)btt*1024 + i4*32 + jb) = v;
            if (t == Tq - 1) *(float4*)(out_sig + (size_t)btt*1024 + i4*32 + jb) = v;
            if (t < Tq - 1) {
                const float4 av = *(const float4*)(outA + (size_t)(btt + 1)*1024 + i4*32 + jb);
                Anx[i4*33 + jb]     = av.x;
                Anx[i4*33 + jb + 1] = av.y;
                Anx[i4*33 + jb + 2] = av.z;
                Anx[i4*33 + jb + 3] = av.w;
                sCn[tid] = outC[(size_t)(btt + 1)*256 + tid];
            }
        }
        if (tid < ZD) {
            float v = sAmu[tid];
            #pragma unroll
            for (int l = 0; l < 8; l++) {
                float kv = 0.f;
                #pragma unroll
                for (int n = 0; n < 8; n++)
                    kv += big[256 + n*32 + tid]*big[768 + n*16 + 8 + l];
                v += kv*serr[l];
            }
            smu[tid] = v;
            g_muf[btt*ZD + tid] = v;
            if (t == Tq - 1) out_mu[btt*ZD + tid] = v;
        }
        __syncthreads();   // B6

        if (t < Tq - 1) {
            // B7 phase (tiled): T1[i4][jb..jb+3] = sum_m Anx[i4][m]*sigf[m][jb..+3]
            {
                float x0 = 0.f, x1 = 0.f, x2 = 0.f, x3 = 0.f;
                #pragma unroll
                for (int m = 0; m < 32; m++) {
                    float av = Anx[i4*33 + m];
                    const float4 s = *(const float4*)&sigf[m*32 + jb];
                    x0 += av*s.x; x1 += av*s.y; x2 += av*s.z; x3 += av*s.w;
                }
                T1b[i4*36 + jb]     = x0;
                T1b[i4*36 + jb + 1] = x1;
                T1b[i4*36 + jb + 2] = x2;
                T1b[i4*36 + jb + 3] = x3;
                float4 r = {x0, x1, x2, x3};
                *(float4*)(g_T1s + (size_t)btt*1024 + i4*32 + jb) = r;
            }
            __syncthreads();   // B7

            // B8 phase (tiled): sigp[i4][jb+s] = Q + sum_m T1[i4][m]*Anx[jb+s][m]
            {
                float a0 = (i4 == jb    ) ? 0.08f : 0.f;
                float a1 = (i4 == jb + 1) ? 0.08f : 0.f;
                float a2 = (i4 == jb + 2) ? 0.08f : 0.f;
                float a3 = (i4 == jb + 3) ? 0.08f : 0.f;
                #pragma unroll
                for (int m4 = 0; m4 < 32; m4 += 4) {
                    const float4 t4 = *(const float4*)&T1b[i4*36 + m4];
                    a0 += t4.x*Anx[(jb    )*33 + m4]     + t4.y*Anx[(jb    )*33 + m4 + 1]
                        + t4.z*Anx[(jb    )*33 + m4 + 2] + t4.w*Anx[(jb    )*33 + m4 + 3];
                    a1 += t4.x*Anx[(jb + 1)*33 + m4]     + t4.y*Anx[(jb + 1)*33 + m4 + 1]
                        + t4.z*Anx[(jb + 1)*33 + m4 + 2] + t4.w*Anx[(jb + 1)*33 + m4 + 3];
                    a2 += t4.x*Anx[(jb + 2)*33 + m4]     + t4.y*Anx[(jb + 2)*33 + m4 + 1]
                        + t4.z*Anx[(jb + 2)*33 + m4 + 2] + t4.w*Anx[(jb + 2)*33 + m4 + 3];
                    a3 += t4.x*Anx[(jb + 3)*33 + m4]     + t4.y*Anx[(jb + 3)*33 + m4 + 1]
                        + t4.z*Anx[(jb + 3)*33 + m4 + 2] + t4.w*Anx[(jb + 3)*33 + m4 + 3];
                }
                sigp[i4*33 + jb]     = a0;
                sigp[i4*33 + jb + 1] = a1;
                sigp[i4*33 + jb + 2] = a2;
                sigp[i4*33 + jb + 3] = a3;
                float4 r = {a0, a1, a2, a3};
                *(float4*)(g_sp + (size_t)btt*1024 + i4*32 + jb) = r;
            }
            __syncthreads();   // B8
        }
    }
}

// =====================================================================
// Kernel 4: batched solves X = sp^{-1} T1 (round-10 verified, unchanged).
// =====================================================================
__global__ void __launch_bounds__(256)
solve_kernel()
{
    const int lin = blockIdx.x;             // 0 .. Bq*(Tq-1)-1
    const int b = lin / (Tq - 1), t = lin % (Tq - 1);
    const size_t bt = (size_t)b*Tq + t;
    const int tid = threadIdx.x;
    const int c = tid >> 2, q = tid & 3;

    __shared__ float Tsh[32*33];
    __shared__ float sfac[2][32];
    __shared__ float spinv[2];

    // stage T1 coalesced -> shared (stride 33; STS conflict-free)
    #pragma unroll
    for (int k = 0; k < 4; k++) {
        int e = tid + 256*k, i = e >> 5, j = e & 31;
        Tsh[i*33 + j] = g_T1s[bt*1024 + e];
    }

    float reg[8];
    if (c < 32) {
        // sp symmetric: column c == row c (contiguous) -> 2 float4 loads
        const float4* bp = (const float4*)(g_sp + bt*1024 + c*32 + q*8);
        float4 r0 = bp[0], r1 = bp[1];
        reg[0] = r0.x; reg[1] = r0.y; reg[2] = r0.z; reg[3] = r0.w;
        reg[4] = r1.x; reg[5] = r1.y; reg[6] = r1.z; reg[7] = r1.w;
    }
    // pivot-0 prep: column 0 snapshot + reciprocal
    if (c == 0) {
        #pragma unroll
        for (int i = 0; i < 8; i++) sfac[0][q*8 + i] = reg[i];
        if (q == 0) spinv[0] = 1.f/reg[0];
    }
    __syncthreads();
    if (c >= 32) {
        // column (c-32) of T1 from padded shared (LDS conflict-free)
        #pragma unroll
        for (int i = 0; i < 8; i++) reg[i] = Tsh[(q*8 + i)*33 + (c - 32)];
    }

    #pragma unroll
    for (int p = 0; p < 32; p++) {
        const int pb = p & 1;
        const float piv = spinv[pb];
        float fac[8];
        #pragma unroll
        for (int i = 0; i < 8; i++) fac[i] = sfac[pb][q*8 + i];
        // row-p element of my column (pre-update), from the lane with q = p>>3
        float m_pc = __shfl_sync(0xffffffffu, reg[p & 7], p >> 3, 4);
        float mn = m_pc * piv;
        if (c > p) {
            #pragma unroll
            for (int i = 0; i < 8; i++) {
                int r = q*8 + i;
                reg[i] = (r == p) ? mn : (reg[i] - fac[i]*mn);
            }
            if (p < 31 && c == p + 1) {
                #pragma unroll
                for (int i = 0; i < 8; i++) sfac[pb ^ 1][q*8 + i] = reg[i];
                if (q == ((p + 1) >> 3)) spinv[pb ^ 1] = 1.f/reg[(p + 1) & 7];
            }
        }
        __syncthreads();
    }

    // stage X through shared (conflict-free STS), write coalesced
    if (c >= 32) {
        #pragma unroll
        for (int i = 0; i < 8; i++) Tsh[(q*8 + i)*33 + (c - 32)] = reg[i];
    }
    __syncthreads();
    #pragma unroll
    for (int k = 0; k < 4; k++) {
        int e = tid + 256*k, i = e >> 5, j = e & 31;
        g_X[bt*1024 + e] = Tsh[i*33 + j];
    }
}

// =====================================================================
// Kernel 5: RTS backward (round-13 verified, unchanged — register
// prefetch pipeline, 3 barriers/step).
// =====================================================================
__global__ void __launch_bounds__(256)
bwd_kernel(float* __restrict__ out_mu, float* __restrict__ out_sig)
{
    __shared__ __align__(16) float X[1024], D[1024], G[1024], Ssn[1024];
    __shared__ float sdm[ZD], smf[ZD], sxv[ZD], smusn[ZD];

    const int b = blockIdx.x, tid = threadIdx.x;
    const int i4 = tid >> 3, jb = (tid & 7) << 2;

    float4 rX, rSp, rSf;       // prefetched values for the CURRENT step
    float  rmp = 0.f, rmf = 0.f;

    {
        const size_t btl = (size_t)b*Tq + (Tq - 1);
        ((float4*)Ssn)[tid] = ((const float4*)(g_sigf + btl*1024))[tid];
        if (tid < ZD) smusn[tid] = g_muf[btl*ZD + tid];
        // prefetch for t = Tq-2
        const size_t bt0 = (size_t)b*Tq + (Tq - 2);
        rX  = ((const float4*)(g_X    + bt0*1024))[tid];
        rSp = ((const float4*)(g_sp   + bt0*1024))[tid];
        rSf = ((const float4*)(g_sigf + bt0*1024))[tid];
        if (tid < ZD) { rmp = g_mp[bt0*ZD + tid]; rmf = g_muf[bt0*ZD + tid]; }
    }
    __syncthreads();

    for (int t = Tq - 2; t >= 0; t--) {
        const size_t bt = (size_t)b*Tq + t;
        // pass0: shared stores from prefetched registers (no global latency)
        ((float4*)X)[tid] = rX;
        {
            float4 s = ((const float4*)Ssn)[tid];
            float4 d = {s.x - rSp.x, s.y - rSp.y, s.z - rSp.z, s.w - rSp.w};
            ((float4*)D)[tid] = d;
        }
        if (tid < ZD) {
            sdm[tid] = smusn[tid] - rmp;
            smf[tid] = rmf;
        }
        __syncthreads();

        // pass A: issue next prefetch FIRST (overlaps compute), then G, xv
        float4 nX, nSp, nSf; float nmp = 0.f, nmf = 0.f;
        if (t > 0) {
            const size_t btn = bt - 1;
            nX  = ((const float4*)(g_X    + btn*1024))[tid];
            nSp = ((const float4*)(g_sp   + btn*1024))[tid];
            nSf = ((const float4*)(g_sigf + btn*1024))[tid];
            if (tid < ZD) { nmp = g_mp[btn*ZD + tid]; nmf = g_muf[btn*ZD + tid]; }
        }
        {
            float g0 = 0, g1 = 0, g2 = 0, g3 = 0;
            #pragma unroll
            for (int m = 0; m < 32; m++) {
                float dv = D[i4*32 + m];
                const float4 xm = *(const float4*)&X[m*32 + jb];
                g0 += dv*xm.x; g1 += dv*xm.y; g2 += dv*xm.z; g3 += dv*xm.w;
            }
            G[i4*32 + jb] = g0; G[i4*32 + jb + 1] = g1;
            G[i4*32 + jb + 2] = g2; G[i4*32 + jb + 3] = g3;
        }
        if (tid < ZD) {
            float v = 0.f;
            #pragma unroll
            for (int k = 0; k < 32; k++) v += X[k*32 + tid]*sdm[k];
            sxv[tid] = v;
        }
        __syncthreads();

        // pass B: sig_s = rSf + X^T G ; mu_s = mf + xv
        {
            float4 acc = rSf;
            #pragma unroll
            for (int k = 0; k < 32; k++) {
                float xk = X[k*32 + i4];
                const float4 g4 = *(const float4*)&G[k*32 + jb];
                acc.x += xk*g4.x; acc.y += xk*g4.y; acc.z += xk*g4.z; acc.w += xk*g4.w;
            }
            ((float4*)(out_sig + bt*1024))[tid] = acc;
            ((float4*)Ssn)[tid] = acc;
        }
        if (tid < ZD) {
            float v = smf[tid] + sxv[tid];
            out_mu[bt*ZD + tid] = v;
            smusn[tid] = v;
        }
        __syncthreads();

        rX = nX; rSp = nSp; rSf = nSf; rmp = nmp; rmf = nmf;
    }
}

// =====================================================================
extern "C" void kernel_launch(void* const* d_in, const int* in_sizes, int n_in,
                              void* d_out, int out_size)
{
    const float* a       = (const float*)d_in[0];
    const float* a1      = (const float*)d_in[1];
    const float* W_ih    = (const float*)d_in[2];
    const float* W_hh    = (const float*)d_in[3];
    const float* b_ih    = (const float*)d_in[4];
    const float* b_hh    = (const float*)d_in[5];
    const float* W_alpha = (const float*)d_in[6];
    const float* b_alpha = (const float*)d_in[7];
    const float* Ag      = (const float*)d_in[8];
    const float* Cg      = (const float*)d_in[9];

    float* out    = (float*)d_out;
    float* out_mu = out;                              // [B,T,32]
    float* out_sg = out_mu + (size_t)BT*ZD;           // [B,T,32,32]
    float* out_A  = out_sg + (size_t)BT*ZD*ZD;        // [B,T,32,32]
    float* out_C  = out_A  + (size_t)BT*ZD*ZD;        // [B,T,8,32]

    lstm_kernel<<<Bq, 256>>>(a, a1, W_ih, W_hh, b_ih, b_hh, W_alpha, b_alpha);
    mix_kernel<<<BT/128, 256>>>(Ag, Cg, out_A, out_C);
    fwd_kernel<<<Bq, 256>>>(a, out_mu, out_sg, out_A, out_C);
    solve_kernel<<<Bq*(Tq - 1), 256>>>();
    bwd_kernel<<<Bq, 256>>>(out_mu, out_sg);
}

// round 15
// speedup vs baseline: 1.2552x; 1.0250x over previous
#include <cuda_runtime.h>

// ---------------- problem constants ----------------
#define Bq   256
#define Tq   128
#define AD   8
#define ZD   32
#define KM   16
#define HIDq 50
#define BT   (Bq*Tq)

// ---------------- device scratch ----------------
__device__ float g_w[BT*KM];
__device__ float g_sigf[(size_t)BT*1024];   // Sigma_f[t]
__device__ float g_T1s[(size_t)BT*1024];    // T1 = A_{t+1} Sigma_f[t]   (slot t, t<=T-2)
__device__ float g_sp[(size_t)BT*1024];     // Sigma_pred[t+1]           (slot t, t<=T-2)
__device__ float g_X[(size_t)BT*1024];      // X = sp^{-1} T1 (= J^T)    (slot t, t<=T-2)
__device__ float g_muf[BT*ZD];              // mu_f[t]
__device__ float g_mp[BT*ZD];               // mu_pred[t+1]              (slot t, t<=T-2)

// =====================================================================
// Kernel 1: LSTM over T + softmax mixture weights (round-14 verified).
// =====================================================================
__global__ void __launch_bounds__(256)
lstm_kernel(const float* __restrict__ a,  const float* __restrict__ a1,
            const float* __restrict__ W_ih, const float* __restrict__ W_hh,
            const float* __restrict__ b_ih, const float* __restrict__ b_hh,
            const float* __restrict__ W_alpha, const float* __restrict__ b_alpha)
{
    __shared__ float sWa[KM*HIDq];
    __shared__ float sh[HIDq], sc[HIDq], sx[2][AD], sg[200];

    const int b = blockIdx.x, tid = threadIdx.x;

    float wi[AD]; float bg = 0.f;
    float whh[HIDq];
    if (tid < 200) {
        #pragma unroll
        for (int j = 0; j < AD; j++) wi[j] = W_ih[tid*AD + j];
        bg = b_ih[tid] + b_hh[tid];
        #pragma unroll
        for (int j = 0; j < HIDq; j++) whh[j] = W_hh[tid*HIDq + j];
    }
    for (int i = tid; i < KM*HIDq; i += 256) sWa[i] = W_alpha[i];
    if (tid < HIDq) { sh[tid] = 0.f; sc[tid] = 0.f; }
    if (tid < AD)   sx[0][tid] = a1[tid];
    __syncthreads();

    for (int t = 0; t < Tq; t++) {
        const float* x = sx[t & 1];
        if (tid < 200) {
            float a0 = bg, a1_ = 0.f, a2 = 0.f, a3 = 0.f;
            #pragma unroll
            for (int j = 0; j < AD; j++) a0 += x[j]*wi[j];
            #pragma unroll
            for (int j = 0; j < 48; j += 4) {
                a0  += sh[j  ]*whh[j  ];
                a1_ += sh[j+1]*whh[j+1];
                a2  += sh[j+2]*whh[j+2];
                a3  += sh[j+3]*whh[j+3];
            }
            a0  += sh[48]*whh[48];
            a1_ += sh[49]*whh[49];
            sg[tid] = (a0 + a1_) + (a2 + a3);
        } else if (tid < 208 && t < Tq - 1) {
            sx[(t + 1) & 1][tid - 200] = a[(b*Tq + t)*AD + (tid - 200)];
        }
        __syncthreads();                 // B2
        if (tid < HIDq) {
            float ig = 1.f/(1.f + __expf(-sg[tid]));
            float fg = 1.f/(1.f + __expf(-sg[HIDq + tid]));
            float gg = tanhf(sg[2*HIDq + tid]);
            float og = 1.f/(1.f + __expf(-sg[3*HIDq + tid]));
            float c  = fg*sc[tid] + ig*gg;
            sc[tid] = c;
            sh[tid] = og*tanhf(c);
        }
        __syncthreads();                 // B3
        if (tid < 32) {
            float logit = -1e30f;
            if (tid < KM) {
                logit = b_alpha[tid];
                #pragma unroll
                for (int j = 0; j < HIDq; j++) logit += sh[j]*sWa[tid*HIDq + j];
            }
            float m = logit;
            #pragma unroll
            for (int d = 8; d; d >>= 1)
                m = fmaxf(m, __shfl_xor_sync(0xffffffffu, m, d, 16));
            float e = __expf(logit - m);
            float s = e;
            #pragma unroll
            for (int d = 8; d; d >>= 1)
                s += __shfl_xor_sync(0xffffffffu, s, d, 16);
            if (tid < KM) g_w[(b*Tq + t)*KM + tid] = e/s;
        }
    }
}

// =====================================================================
// Kernel 2: A_t/C_t mixing (verified, unchanged).
// =====================================================================
__global__ void __launch_bounds__(256)
mix_kernel(const float* __restrict__ Ag, const float* __restrict__ Cg,
           float* __restrict__ outA, float* __restrict__ outC)
{
    __shared__ float sw[128*KM];
    const int tid = threadIdx.x;
    const int r0  = blockIdx.x * 128;
    for (int i = tid; i < 128*KM; i += 256) sw[i] = g_w[r0*KM + i];
    __syncthreads();

    for (int c = tid; c < 1280; c += 256) {
        float av[KM];
        if (c < 1024) {
            #pragma unroll
            for (int k = 0; k < KM; k++) av[k] = Ag[k*1024 + c];
            for (int r = 0; r < 128; r++) {
                float acc = 0.f;
                #pragma unroll
                for (int k = 0; k < KM; k++) acc += sw[r*KM + k]*av[k];
                outA[(size_t)(r0 + r)*1024 + c] = acc;
            }
        } else {
            const int cc = c - 1024;
            #pragma unroll
            for (int k = 0; k < KM; k++) av[k] = Cg[k*256 + cc];
            for (int r = 0; r < 128; r++) {
                float acc = 0.f;
                #pragma unroll
                for (int k = 0; k < KM; k++) acc += sw[r*KM + k]*av[k];
                outC[(r0 + r)*256 + cc] = acc;
            }
        }
    }
}

// =====================================================================
// Kernel 3: Kalman forward filter — round-14 verified math, 5 barrier
// phases/step, NOW with a REGISTER PREFETCH pipeline: A_{t+1}, C_{t+1},
// and y_t are LDG'd into registers at the TOP of step t (latency hidden
// behind B2+B34 compute); B6 stores them to shared from registers.
// Kg from Pt (rows of sigp) — load-bearing for stability.
// =====================================================================
__global__ void __launch_bounds__(256)
fwd_kernel(const float* __restrict__ a,
           float* __restrict__ out_mu, float* __restrict__ out_sig,
           const float* __restrict__ outA, const float* __restrict__ outC)
{
    __shared__ float sAbuf[2*1056];                 // ping-pong A (stride 33)
    __shared__ float sC2[2][256];                   // double-buffered C_t [8][32]
    __shared__ float sigp[1056];                    // sig_pred (stride 33)
    __shared__ __align__(16) float sigf[1024];      // sig_filt (stride 32)
    __shared__ __align__(16) float big[1024];       // M1 | Pt | (unused) | aug8
    __shared__ __align__(16) float T1b[32*36];      // T1 (stride 36)
    __shared__ float sAmu[ZD], serr[AD], smu[ZD];

    const int b = blockIdx.x, tid = threadIdx.x;
    const int i4 = tid >> 3;                // tiled-output row (0..31)
    const int jb = (tid & 7) << 2;          // tiled-output col block (x4)

    // ---- init: sig_pred = 20*I, mu = 0, load A_t[b][0], C_t[b][0] ----
    for (int e = tid; e < 1024; e += 256) {
        int i = e >> 5, j = e & 31;
        sigp[i*33 + j] = (i == j) ? 20.f : 0.f;
        sAbuf[i*33 + j] = outA[(size_t)(b*Tq)*1024 + e];
    }
    sC2[0][tid] = outC[(size_t)(b*Tq)*256 + tid];
    if (tid < ZD) smu[tid] = 0.f;
    __syncthreads();

    for (int t = 0; t < Tq; t++) {
        float* Ac  = sAbuf + (t & 1)*1056;
        float* Anx = sAbuf + ((t + 1) & 1)*1056;
        const float* sC  = sC2[t & 1];
        float*       sCn = sC2[(t + 1) & 1];
        const int btt = b*Tq + t;

        // ---- TOP: issue next-step prefetch LDGs (consumed at B34/B6) ----
        float4 rA; float rC = 0.f, ry = 0.f;
        if (t < Tq - 1) {
            rA = *(const float4*)(outA + (size_t)(btt + 1)*1024 + i4*32 + jb);
            rC = outC[(size_t)(btt + 1)*256 + tid];
        }
        if (tid >= 64 && tid < 72) ry = a[(size_t)btt*AD + (tid - 64)];

        // B2 phase: M1 = C @ sigp ; Pt[l][j] = (sigp C^T)[j][l]
        //           + Amu = Ac @ mu (tid<32)
        {
            int l = tid >> 5, j = tid & 31;
            float acc = 0.f;
            #pragma unroll
            for (int m = 0; m < 32; m++) acc += sC[l*32 + m]*sigp[m*33 + j];
            big[l*32 + j] = acc;
            float acc2 = 0.f;
            #pragma unroll
            for (int m = 0; m < 32; m++) acc2 += sigp[j*33 + m]*sC[l*32 + m];
            big[256 + l*32 + j] = acc2;
        }
        if (tid < ZD) {
            float acc = 0.f;
            #pragma unroll
            for (int m = 0; m < 32; m++) acc += Ac[tid*33 + m]*smu[m];
            sAmu[tid] = acc;
            if (t > 0) g_mp[(btt - 1)*ZD + tid] = acc;  // mu_pred[t] at slot t-1
        }
        __syncthreads();   // B2

        // B34 phase: warp0 = S aug then invert; tid 64..71 = err (uses ry)
        if (tid < 32) {
            #pragma unroll
            for (int h = 0; h < 2; h++) {
                int o = tid + 32*h;
                int l = o >> 3, n = o & 7;
                float acc = 0.f;
                #pragma unroll
                for (int m = 0; m < 32; m++) acc += big[l*32 + m]*sC[n*32 + m];
                big[768 + l*16 + n]     = acc + ((l == n) ? 0.03f : 0.f);
                big[768 + l*16 + 8 + n] = (l == n) ? 1.f : 0.f;
            }
            __syncwarp();
            // invert 8x8 SPD (Gauss-Jordan, verified)
            int r = tid >> 2, c0 = (tid & 3)*4;
            #pragma unroll
            for (int p = 0; p < 8; p++) {
                float fc  = big[768 + r*16 + p];
                float p0 = big[768 + p*16 + c0];
                float p1 = big[768 + p*16 + c0 + 1];
                float p2 = big[768 + p*16 + c0 + 2];
                float p3 = big[768 + p*16 + c0 + 3];
                float pd = big[768 + p*16 + p];
                __syncwarp();
                float pinv = 1.f/pd;
                if (r == p) {
                    big[768 + r*16 + c0]     = p0*pinv;
                    big[768 + r*16 + c0 + 1] = p1*pinv;
                    big[768 + r*16 + c0 + 2] = p2*pinv;
                    big[768 + r*16 + c0 + 3] = p3*pinv;
                } else {
                    float f = fc*pinv;
                    big[768 + r*16 + c0]     -= f*p0;
                    big[768 + r*16 + c0 + 1] -= f*p1;
                    big[768 + r*16 + c0 + 2] -= f*p2;
                    big[768 + r*16 + c0 + 3] -= f*p3;
                }
                __syncwarp();
            }
        } else if (tid >= 64 && tid < 72) {
            int l = tid - 64;
            float acc = 0.f;
            #pragma unroll
            for (int m = 0; m < 32; m++) acc += sC[l*32 + m]*sAmu[m];
            serr[l] = ry - acc;
        }
        __syncthreads();   // B34

        // B6 phase (tiled): local kg; sigf row i4 cols jb..jb+3;
        // STS prefetched A_{t+1}, C_{t+1}; mu_f (tid<32, local kg)
        {
            float kg[8];
            #pragma unroll
            for (int l = 0; l < 8; l++) {
                float acc = 0.f;
                #pragma unroll
                for (int n = 0; n < 8; n++)
                    acc += big[256 + n*32 + i4]*big[768 + n*16 + 8 + l];
                kg[l] = acc;
            }
            float4 v = {sigp[i4*33 + jb],     sigp[i4*33 + jb + 1],
                        sigp[i4*33 + jb + 2], sigp[i4*33 + jb + 3]};
            #pragma unroll
            for (int l = 0; l < 8; l++) {
                float k = kg[l];
                const float4 m = *(const float4*)&big[l*32 + jb];
                v.x -= k*m.x; v.y -= k*m.y; v.z -= k*m.z; v.w -= k*m.w;
            }
            *(float4*)&sigf[i4*32 + jb] = v;
            *(float4*)(g_sigf + (size_t)btt*1024 + i4*32 + jb) = v;
            if (t == Tq - 1) *(float4*)(out_sig + (size_t)btt*1024 + i4*32 + jb) = v;
            if (t < Tq - 1) {
                Anx[i4*33 + jb]     = rA.x;
                Anx[i4*33 + jb + 1] = rA.y;
                Anx[i4*33 + jb + 2] = rA.z;
                Anx[i4*33 + jb + 3] = rA.w;
                sCn[tid] = rC;
            }
        }
        if (tid < ZD) {
            float v = sAmu[tid];
            #pragma unroll
            for (int l = 0; l < 8; l++) {
                float kv = 0.f;
                #pragma unroll
                for (int n = 0; n < 8; n++)
                    kv += big[256 + n*32 + tid]*big[768 + n*16 + 8 + l];
                v += kv*serr[l];
            }
            smu[tid] = v;
            g_muf[btt*ZD + tid] = v;
            if (t == Tq - 1) out_mu[btt*ZD + tid] = v;
        }
        __syncthreads();   // B6

        if (t < Tq - 1) {
            // B7 phase (tiled): T1[i4][jb..jb+3] = sum_m Anx[i4][m]*sigf[m][jb..+3]
            {
                float x0 = 0.f, x1 = 0.f, x2 = 0.f, x3 = 0.f;
                #pragma unroll
                for (int m = 0; m < 32; m++) {
                    float av = Anx[i4*33 + m];
                    const float4 s = *(const float4*)&sigf[m*32 + jb];
                    x0 += av*s.x; x1 += av*s.y; x2 += av*s.z; x3 += av*s.w;
                }
                T1b[i4*36 + jb]     = x0;
                T1b[i4*36 + jb + 1] = x1;
                T1b[i4*36 + jb + 2] = x2;
                T1b[i4*36 + jb + 3] = x3;
                float4 r = {x0, x1, x2, x3};
                *(float4*)(g_T1s + (size_t)btt*1024 + i4*32 + jb) = r;
            }
            __syncthreads();   // B7

            // B8 phase (tiled): sigp[i4][jb+s] = Q + sum_m T1[i4][m]*Anx[jb+s][m]
            {
                float a0 = (i4 == jb    ) ? 0.08f : 0.f;
                float a1 = (i4 == jb + 1) ? 0.08f : 0.f;
                float a2 = (i4 == jb + 2) ? 0.08f : 0.f;
                float a3 = (i4 == jb + 3) ? 0.08f : 0.f;
                #pragma unroll
                for (int m4 = 0; m4 < 32; m4 += 4) {
                    const float4 t4 = *(const float4*)&T1b[i4*36 + m4];
                    a0 += t4.x*Anx[(jb    )*33 + m4]     + t4.y*Anx[(jb    )*33 + m4 + 1]
                        + t4.z*Anx[(jb    )*33 + m4 + 2] + t4.w*Anx[(jb    )*33 + m4 + 3];
                    a1 += t4.x*Anx[(jb + 1)*33 + m4]     + t4.y*Anx[(jb + 1)*33 + m4 + 1]
                        + t4.z*Anx[(jb + 1)*33 + m4 + 2] + t4.w*Anx[(jb + 1)*33 + m4 + 3];
                    a2 += t4.x*Anx[(jb + 2)*33 + m4]     + t4.y*Anx[(jb + 2)*33 + m4 + 1]
                        + t4.z*Anx[(jb + 2)*33 + m4 + 2] + t4.w*Anx[(jb + 2)*33 + m4 + 3];
                    a3 += t4.x*Anx[(jb + 3)*33 + m4]     + t4.y*Anx[(jb + 3)*33 + m4 + 1]
                        + t4.z*Anx[(jb + 3)*33 + m4 + 2] + t4.w*Anx[(jb + 3)*33 + m4 + 3];
                }
                sigp[i4*33 + jb]     = a0;
                sigp[i4*33 + jb + 1] = a1;
                sigp[i4*33 + jb + 2] = a2;
                sigp[i4*33 + jb + 3] = a3;
                float4 r = {a0, a1, a2, a3};
                *(float4*)(g_sp + (size_t)btt*1024 + i4*32 + jb) = r;
            }
            __syncthreads();   // B8
        }
    }
}

// =====================================================================
// Kernel 4: batched solves X = sp^{-1} T1 (round-10 verified, unchanged).
// =====================================================================
__global__ void __launch_bounds__(256)
solve_kernel()
{
    const int lin = blockIdx.x;             // 0 .. Bq*(Tq-1)-1
    const int b = lin / (Tq - 1), t = lin % (Tq - 1);
    const size_t bt = (size_t)b*Tq + t;
    const int tid = threadIdx.x;
    const int c = tid >> 2, q = tid & 3;

    __shared__ float Tsh[32*33];
    __shared__ float sfac[2][32];
    __shared__ float spinv[2];

    // stage T1 coalesced -> shared (stride 33; STS conflict-free)
    #pragma unroll
    for (int k = 0; k < 4; k++) {
        int e = tid + 256*k, i = e >> 5, j = e & 31;
        Tsh[i*33 + j] = g_T1s[bt*1024 + e];
    }

    float reg[8];
    if (c < 32) {
        // sp symmetric: column c == row c (contiguous) -> 2 float4 loads
        const float4* bp = (const float4*)(g_sp + bt*1024 + c*32 + q*8);
        float4 r0 = bp[0], r1 = bp[1];
        reg[0] = r0.x; reg[1] = r0.y; reg[2] = r0.z; reg[3] = r0.w;
        reg[4] = r1.x; reg[5] = r1.y; reg[6] = r1.z; reg[7] = r1.w;
    }
    // pivot-0 prep: column 0 snapshot + reciprocal
    if (c == 0) {
        #pragma unroll
        for (int i = 0; i < 8; i++) sfac[0][q*8 + i] = reg[i];
        if (q == 0) spinv[0] = 1.f/reg[0];
    }
    __syncthreads();
    if (c >= 32) {
        // column (c-32) of T1 from padded shared (LDS conflict-free)
        #pragma unroll
        for (int i = 0; i < 8; i++) reg[i] = Tsh[(q*8 + i)*33 + (c - 32)];
    }

    #pragma unroll
    for (int p = 0; p < 32; p++) {
        const int pb = p & 1;
        const float piv = spinv[pb];
        float fac[8];
        #pragma unroll
        for (int i = 0; i < 8; i++) fac[i] = sfac[pb][q*8 + i];
        // row-p element of my column (pre-update), from the lane with q = p>>3
        float m_pc = __shfl_sync(0xffffffffu, reg[p & 7], p >> 3, 4);
        float mn = m_pc * piv;
        if (c > p) {
            #pragma unroll
            for (int i = 0; i < 8; i++) {
                int r = q*8 + i;
                reg[i] = (r == p) ? mn : (reg[i] - fac[i]*mn);
            }
            if (p < 31 && c == p + 1) {
                #pragma unroll
                for (int i = 0; i < 8; i++) sfac[pb ^ 1][q*8 + i] = reg[i];
                if (q == ((p + 1) >> 3)) spinv[pb ^ 1] = 1.f/reg[(p + 1) & 7];
            }
        }
        __syncthreads();
    }

    // stage X through shared (conflict-free STS), write coalesced
    if (c >= 32) {
        #pragma unroll
        for (int i = 0; i < 8; i++) Tsh[(q*8 + i)*33 + (c - 32)] = reg[i];
    }
    __syncthreads();
    #pragma unroll
    for (int k = 0; k < 4; k++) {
        int e = tid + 256*k, i = e >> 5, j = e & 31;
        g_X[bt*1024 + e] = Tsh[i*33 + j];
    }
}

// =====================================================================
// Kernel 5: RTS backward (round-13 verified, unchanged — register
// prefetch pipeline, 3 barriers/step).
// =====================================================================
__global__ void __launch_bounds__(256)
bwd_kernel(float* __restrict__ out_mu, float* __restrict__ out_sig)
{
    __shared__ __align__(16) float X[1024], D[1024], G[1024], Ssn[1024];
    __shared__ float sdm[ZD], smf[ZD], sxv[ZD], smusn[ZD];

    const int b = blockIdx.x, tid = threadIdx.x;
    const int i4 = tid >> 3, jb = (tid & 7) << 2;

    float4 rX, rSp, rSf;       // prefetched values for the CURRENT step
    float  rmp = 0.f, rmf = 0.f;

    {
        const size_t btl = (size_t)b*Tq + (Tq - 1);
        ((float4*)Ssn)[tid] = ((const float4*)(g_sigf + btl*1024))[tid];
        if (tid < ZD) smusn[tid] = g_muf[btl*ZD + tid];
        // prefetch for t = Tq-2
        const size_t bt0 = (size_t)b*Tq + (Tq - 2);
        rX  = ((const float4*)(g_X    + bt0*1024))[tid];
        rSp = ((const float4*)(g_sp   + bt0*1024))[tid];
        rSf = ((const float4*)(g_sigf + bt0*1024))[tid];
        if (tid < ZD) { rmp = g_mp[bt0*ZD + tid]; rmf = g_muf[bt0*ZD + tid]; }
    }
    __syncthreads();

    for (int t = Tq - 2; t >= 0; t--) {
        const size_t bt = (size_t)b*Tq + t;
        // pass0: shared stores from prefetched registers (no global latency)
        ((float4*)X)[tid] = rX;
        {
            float4 s = ((const float4*)Ssn)[tid];
            float4 d = {s.x - rSp.x, s.y - rSp.y, s.z - rSp.z, s.w - rSp.w};
            ((float4*)D)[tid] = d;
        }
        if (tid < ZD) {
            sdm[tid] = smusn[tid] - rmp;
            smf[tid] = rmf;
        }
        __syncthreads();

        // pass A: issue next prefetch FIRST (overlaps compute), then G, xv
        float4 nX, nSp, nSf; float nmp = 0.f, nmf = 0.f;
        if (t > 0) {
            const size_t btn = bt - 1;
            nX  = ((const float4*)(g_X    + btn*1024))[tid];
            nSp = ((const float4*)(g_sp   + btn*1024))[tid];
            nSf = ((const float4*)(g_sigf + btn*1024))[tid];
            if (tid < ZD) { nmp = g_mp[btn*ZD + tid]; nmf = g_muf[btn*ZD + tid]; }
        }
        {
            float g0 = 0, g1 = 0, g2 = 0, g3 = 0;
            #pragma unroll
            for (int m = 0; m < 32; m++) {
                float dv = D[i4*32 + m];
                const float4 xm = *(const float4*)&X[m*32 + jb];
                g0 += dv*xm.x; g1 += dv*xm.y; g2 += dv*xm.z; g3 += dv*xm.w;
            }
            G[i4*32 + jb] = g0; G[i4*32 + jb + 1] = g1;
            G[i4*32 + jb + 2] = g2; G[i4*32 + jb + 3] = g3;
        }
        if (tid < ZD) {
            float v = 0.f;
            #pragma unroll
            for (int k = 0; k < 32; k++) v += X[k*32 + tid]*sdm[k];
            sxv[tid] = v;
        }
        __syncthreads();

        // pass B: sig_s = rSf + X^T G ; mu_s = mf + xv
        {
            float4 acc = rSf;
            #pragma unroll
            for (int k = 0; k < 32; k++) {
                float xk = X[k*32 + i4];
                const float4 g4 = *(const float4*)&G[k*32 + jb];
                acc.x += xk*g4.x; acc.y += xk*g4.y; acc.z += xk*g4.z; acc.w += xk*g4.w;
            }
            ((float4*)(out_sig + bt*1024))[tid] = acc;
            ((float4*)Ssn)[tid] = acc;
        }
        if (tid < ZD) {
            float v = smf[tid] + sxv[tid];
            out_mu[bt*ZD + tid] = v;
            smusn[tid] = v;
        }
        __syncthreads();

        rX = nX; rSp = nSp; rSf = nSf; rmp = nmp; rmf = nmf;
    }
}

// =====================================================================
extern "C" void kernel_launch(void* const* d_in, const int* in_sizes, int n_in,
                              void* d_out, int out_size)
{
    const float* a       = (const float*)d_in[0];
    const float* a1      = (const float*)d_in[1];
    const float* W_ih    = (const float*)d_in[2];
    const float* W_hh    = (const float*)d_in[3];
    const float* b_ih    = (const float*)d_in[4];
    const float* b_hh    = (const float*)d_in[5];
    const float* W_alpha = (const float*)d_in[6];
    const float* b_alpha = (const float*)d_in[7];
    const float* Ag      = (const float*)d_in[8];
    const float* Cg      = (const float*)d_in[9];

    float* out    = (float*)d_out;
    float* out_mu = out;                              // [B,T,32]
    float* out_sg = out_mu + (size_t)BT*ZD;           // [B,T,32,32]
    float* out_A  = out_sg + (size_t)BT*ZD*ZD;        // [B,T,32,32]
    float* out_C  = out_A  + (size_t)BT*ZD*ZD;        // [B,T,8,32]

    lstm_kernel<<<Bq, 256>>>(a, a1, W_ih, W_hh, b_ih, b_hh, W_alpha, b_alpha);
    mix_kernel<<<BT/128, 256>>>(Ag, Cg, out_A, out_C);
    fwd_kernel<<<Bq, 256>>>(a, out_mu, out_sg, out_A, out_C);
    solve_kernel<<<Bq*(Tq - 1), 256>>>();
    bwd_kernel<<<Bq, 256>>>(out_mu, out_sg);
}

// round 16
// speedup vs baseline: 1.2782x; 1.0183x over previous
#include <cuda_runtime.h>

// ---------------- problem constants ----------------
#define Bq   256
#define Tq   128
#define AD   8
#define ZD   32
#define KM   16
#define HIDq 50
#define BT   (Bq*Tq)

// ---------------- device scratch ----------------
__device__ float g_w[BT*KM];
__device__ float g_sigf[(size_t)BT*1024];   // Sigma_f[t]
__device__ float g_T1s[(size_t)BT*1024];    // T1 = A_{t+1} Sigma_f[t]   (slot t, t<=T-2)
__device__ float g_sp[(size_t)BT*1024];     // Sigma_pred[t+1]           (slot t, t<=T-2)
__device__ float g_X[(size_t)BT*1024];      // X = sp^{-1} T1 (= J^T)    (slot t, t<=T-2)
__device__ float g_muf[BT*ZD];              // mu_f[t]
__device__ float g_mp[BT*ZD];               // mu_pred[t+1]              (slot t, t<=T-2)

// =====================================================================
// Kernel 1: LSTM over T + softmax mixture weights (round-15 verified).
// =====================================================================
__global__ void __launch_bounds__(256)
lstm_kernel(const float* __restrict__ a,  const float* __restrict__ a1,
            const float* __restrict__ W_ih, const float* __restrict__ W_hh,
            const float* __restrict__ b_ih, const float* __restrict__ b_hh,
            const float* __restrict__ W_alpha, const float* __restrict__ b_alpha)
{
    __shared__ float sWa[KM*HIDq];
    __shared__ float sh[HIDq], sc[HIDq], sx[2][AD], sg[200];

    const int b = blockIdx.x, tid = threadIdx.x;

    float wi[AD]; float bg = 0.f;
    float whh[HIDq];
    if (tid < 200) {
        #pragma unroll
        for (int j = 0; j < AD; j++) wi[j] = W_ih[tid*AD + j];
        bg = b_ih[tid] + b_hh[tid];
        #pragma unroll
        for (int j = 0; j < HIDq; j++) whh[j] = W_hh[tid*HIDq + j];
    }
    for (int i = tid; i < KM*HIDq; i += 256) sWa[i] = W_alpha[i];
    if (tid < HIDq) { sh[tid] = 0.f; sc[tid] = 0.f; }
    if (tid < AD)   sx[0][tid] = a1[tid];
    __syncthreads();

    for (int t = 0; t < Tq; t++) {
        const float* x = sx[t & 1];
        if (tid < 200) {
            float a0 = bg, a1_ = 0.f, a2 = 0.f, a3 = 0.f;
            #pragma unroll
            for (int j = 0; j < AD; j++) a0 += x[j]*wi[j];
            #pragma unroll
            for (int j = 0; j < 48; j += 4) {
                a0  += sh[j  ]*whh[j  ];
                a1_ += sh[j+1]*whh[j+1];
                a2  += sh[j+2]*whh[j+2];
                a3  += sh[j+3]*whh[j+3];
            }
            a0  += sh[48]*whh[48];
            a1_ += sh[49]*whh[49];
            sg[tid] = (a0 + a1_) + (a2 + a3);
        } else if (tid < 208 && t < Tq - 1) {
            sx[(t + 1) & 1][tid - 200] = a[(b*Tq + t)*AD + (tid - 200)];
        }
        __syncthreads();                 // B2
        if (tid < HIDq) {
            float ig = 1.f/(1.f + __expf(-sg[tid]));
            float fg = 1.f/(1.f + __expf(-sg[HIDq + tid]));
            float gg = tanhf(sg[2*HIDq + tid]);
            float og = 1.f/(1.f + __expf(-sg[3*HIDq + tid]));
            float c  = fg*sc[tid] + ig*gg;
            sc[tid] = c;
            sh[tid] = og*tanhf(c);
        }
        __syncthreads();                 // B3
        if (tid < 32) {
            float logit = -1e30f;
            if (tid < KM) {
                logit = b_alpha[tid];
                #pragma unroll
                for (int j = 0; j < HIDq; j++) logit += sh[j]*sWa[tid*HIDq + j];
            }
            float m = logit;
            #pragma unroll
            for (int d = 8; d; d >>= 1)
                m = fmaxf(m, __shfl_xor_sync(0xffffffffu, m, d, 16));
            float e = __expf(logit - m);
            float s = e;
            #pragma unroll
            for (int d = 8; d; d >>= 1)
                s += __shfl_xor_sync(0xffffffffu, s, d, 16);
            if (tid < KM) g_w[(b*Tq + t)*KM + tid] = e/s;
        }
    }
}

// =====================================================================
// Kernel 2: A_t/C_t mixing (verified, unchanged).
// =====================================================================
__global__ void __launch_bounds__(256)
mix_kernel(const float* __restrict__ Ag, const float* __restrict__ Cg,
           float* __restrict__ outA, float* __restrict__ outC)
{
    __shared__ float sw[128*KM];
    const int tid = threadIdx.x;
    const int r0  = blockIdx.x * 128;
    for (int i = tid; i < 128*KM; i += 256) sw[i] = g_w[r0*KM + i];
    __syncthreads();

    for (int c = tid; c < 1280; c += 256) {
        float av[KM];
        if (c < 1024) {
            #pragma unroll
            for (int k = 0; k < KM; k++) av[k] = Ag[k*1024 + c];
            for (int r = 0; r < 128; r++) {
                float acc = 0.f;
                #pragma unroll
                for (int k = 0; k < KM; k++) acc += sw[r*KM + k]*av[k];
                outA[(size_t)(r0 + r)*1024 + c] = acc;
            }
        } else {
            const int cc = c - 1024;
            #pragma unroll
            for (int k = 0; k < KM; k++) av[k] = Cg[k*256 + cc];
            for (int r = 0; r < 128; r++) {
                float acc = 0.f;
                #pragma unroll
                for (int k = 0; k < KM; k++) acc += sw[r*KM + k]*av[k];
                outC[(r0 + r)*256 + cc] = acc;
            }
        }
    }
}

// =====================================================================
// Kernel 3: Kalman forward filter — round-15 verified math; the
// Anx/sCn prefetch STS for warps {1,3..7} moved into the B34 phase
// (overlaps warp0's serial inversion); warps 0 and the err-group keep
// their STS in B6. Disjoint element sets, identical arithmetic.
// Kg from Pt (rows of sigp) — load-bearing for stability.
// =====================================================================
__global__ void __launch_bounds__(256)
fwd_kernel(const float* __restrict__ a,
           float* __restrict__ out_mu, float* __restrict__ out_sig,
           const float* __restrict__ outA, const float* __restrict__ outC)
{
    __shared__ float sAbuf[2*1056];                 // ping-pong A (stride 33)
    __shared__ float sC2[2][256];                   // double-buffered C_t [8][32]
    __shared__ float sigp[1056];                    // sig_pred (stride 33)
    __shared__ __align__(16) float sigf[1024];      // sig_filt (stride 32)
    __shared__ __align__(16) float big[1024];       // M1 | Pt | (unused) | aug8
    __shared__ __align__(16) float T1b[32*36];      // T1 (stride 36)
    __shared__ float sAmu[ZD], serr[AD], smu[ZD];

    const int b = blockIdx.x, tid = threadIdx.x;
    const int i4 = tid >> 3;                // tiled-output row (0..31)
    const int jb = (tid & 7) << 2;          // tiled-output col block (x4)
    const bool early_pf = !(tid < 32 || (tid >= 64 && tid < 72));

    // ---- init: sig_pred = 20*I, mu = 0, load A_t[b][0], C_t[b][0] ----
    for (int e = tid; e < 1024; e += 256) {
        int i = e >> 5, j = e & 31;
        sigp[i*33 + j] = (i == j) ? 20.f : 0.f;
        sAbuf[i*33 + j] = outA[(size_t)(b*Tq)*1024 + e];
    }
    sC2[0][tid] = outC[(size_t)(b*Tq)*256 + tid];
    if (tid < ZD) smu[tid] = 0.f;
    __syncthreads();

    for (int t = 0; t < Tq; t++) {
        float* Ac  = sAbuf + (t & 1)*1056;
        float* Anx = sAbuf + ((t + 1) & 1)*1056;
        const float* sC  = sC2[t & 1];
        float*       sCn = sC2[(t + 1) & 1];
        const int btt = b*Tq + t;

        // ---- TOP: issue next-step prefetch LDGs ----
        float4 rA; float rC = 0.f, ry = 0.f;
        if (t < Tq - 1) {
            rA = *(const float4*)(outA + (size_t)(btt + 1)*1024 + i4*32 + jb);
            rC = outC[(size_t)(btt + 1)*256 + tid];
        }
        if (tid >= 64 && tid < 72) ry = a[(size_t)btt*AD + (tid - 64)];

        // B2 phase: M1 = C @ sigp ; Pt[l][j] = (sigp C^T)[j][l]
        //           + Amu = Ac @ mu (tid<32)
        {
            int l = tid >> 5, j = tid & 31;
            float acc = 0.f;
            #pragma unroll
            for (int m = 0; m < 32; m++) acc += sC[l*32 + m]*sigp[m*33 + j];
            big[l*32 + j] = acc;
            float acc2 = 0.f;
            #pragma unroll
            for (int m = 0; m < 32; m++) acc2 += sigp[j*33 + m]*sC[l*32 + m];
            big[256 + l*32 + j] = acc2;
        }
        if (tid < ZD) {
            float acc = 0.f;
            #pragma unroll
            for (int m = 0; m < 32; m++) acc += Ac[tid*33 + m]*smu[m];
            sAmu[tid] = acc;
            if (t > 0) g_mp[(btt - 1)*ZD + tid] = acc;  // mu_pred[t] at slot t-1
        }
        __syncthreads();   // B2

        // B34 phase: warp0 = S aug then invert; tid 64..71 = err;
        //            remaining threads STS their prefetched A/C rows
        if (tid < 32) {
            #pragma unroll
            for (int h = 0; h < 2; h++) {
                int o = tid + 32*h;
                int l = o >> 3, n = o & 7;
                float acc = 0.f;
                #pragma unroll
                for (int m = 0; m < 32; m++) acc += big[l*32 + m]*sC[n*32 + m];
                big[768 + l*16 + n]     = acc + ((l == n) ? 0.03f : 0.f);
                big[768 + l*16 + 8 + n] = (l == n) ? 1.f : 0.f;
            }
            __syncwarp();
            // invert 8x8 SPD (Gauss-Jordan, verified)
            int r = tid >> 2, c0 = (tid & 3)*4;
            #pragma unroll
            for (int p = 0; p < 8; p++) {
                float fc  = big[768 + r*16 + p];
                float p0 = big[768 + p*16 + c0];
                float p1 = big[768 + p*16 + c0 + 1];
                float p2 = big[768 + p*16 + c0 + 2];
                float p3 = big[768 + p*16 + c0 + 3];
                float pd = big[768 + p*16 + p];
                __syncwarp();
                float pinv = 1.f/pd;
                if (r == p) {
                    big[768 + r*16 + c0]     = p0*pinv;
                    big[768 + r*16 + c0 + 1] = p1*pinv;
                    big[768 + r*16 + c0 + 2] = p2*pinv;
                    big[768 + r*16 + c0 + 3] = p3*pinv;
                } else {
                    float f = fc*pinv;
                    big[768 + r*16 + c0]     -= f*p0;
                    big[768 + r*16 + c0 + 1] -= f*p1;
                    big[768 + r*16 + c0 + 2] -= f*p2;
                    big[768 + r*16 + c0 + 3] -= f*p3;
                }
                __syncwarp();
            }
        } else if (tid >= 64 && tid < 72) {
            int l = tid - 64;
            float acc = 0.f;
            #pragma unroll
            for (int m = 0; m < 32; m++) acc += sC[l*32 + m]*sAmu[m];
            serr[l] = ry - acc;
        } else if (t < Tq - 1) {
            // early prefetch STS (overlaps warp0's inversion)
            Anx[i4*33 + jb]     = rA.x;
            Anx[i4*33 + jb + 1] = rA.y;
            Anx[i4*33 + jb + 2] = rA.z;
            Anx[i4*33 + jb + 3] = rA.w;
            sCn[tid] = rC;
        }
        __syncthreads();   // B34

        // B6 phase (tiled): local kg; sigf row i4 cols jb..jb+3;
        // leftover prefetch STS (warp0 + err group); mu_f (tid<32)
        {
            float kg[8];
            #pragma unroll
            for (int l = 0; l < 8; l++) {
                float acc = 0.f;
                #pragma unroll
                for (int n = 0; n < 8; n++)
                    acc += big[256 + n*32 + i4]*big[768 + n*16 + 8 + l];
                kg[l] = acc;
            }
            float4 v = {sigp[i4*33 + jb],     sigp[i4*33 + jb + 1],
                        sigp[i4*33 + jb + 2], sigp[i4*33 + jb + 3]};
            #pragma unroll
            for (int l = 0; l < 8; l++) {
                float k = kg[l];
                const float4 m = *(const float4*)&big[l*32 + jb];
                v.x -= k*m.x; v.y -= k*m.y; v.z -= k*m.z; v.w -= k*m.w;
            }
            *(float4*)&sigf[i4*32 + jb] = v;
            *(float4*)(g_sigf + (size_t)btt*1024 + i4*32 + jb) = v;
            if (t == Tq - 1) *(float4*)(out_sig + (size_t)btt*1024 + i4*32 + jb) = v;
            if (t < Tq - 1 && !early_pf) {
                Anx[i4*33 + jb]     = rA.x;
                Anx[i4*33 + jb + 1] = rA.y;
                Anx[i4*33 + jb + 2] = rA.z;
                Anx[i4*33 + jb + 3] = rA.w;
                sCn[tid] = rC;
            }
        }
        if (tid < ZD) {
            float v = sAmu[tid];
            #pragma unroll
            for (int l = 0; l < 8; l++) {
                float kv = 0.f;
                #pragma unroll
                for (int n = 0; n < 8; n++)
                    kv += big[256 + n*32 + tid]*big[768 + n*16 + 8 + l];
                v += kv*serr[l];
            }
            smu[tid] = v;
            g_muf[btt*ZD + tid] = v;
            if (t == Tq - 1) out_mu[btt*ZD + tid] = v;
        }
        __syncthreads();   // B6

        if (t < Tq - 1) {
            // B7 phase (tiled): T1[i4][jb..jb+3] = sum_m Anx[i4][m]*sigf[m][jb..+3]
            {
                float x0 = 0.f, x1 = 0.f, x2 = 0.f, x3 = 0.f;
                #pragma unroll
                for (int m = 0; m < 32; m++) {
                    float av = Anx[i4*33 + m];
                    const float4 s = *(const float4*)&sigf[m*32 + jb];
                    x0 += av*s.x; x1 += av*s.y; x2 += av*s.z; x3 += av*s.w;
                }
                T1b[i4*36 + jb]     = x0;
                T1b[i4*36 + jb + 1] = x1;
                T1b[i4*36 + jb + 2] = x2;
                T1b[i4*36 + jb + 3] = x3;
                float4 r = {x0, x1, x2, x3};
                *(float4*)(g_T1s + (size_t)btt*1024 + i4*32 + jb) = r;
            }
            __syncthreads();   // B7

            // B8 phase (tiled): sigp[i4][jb+s] = Q + sum_m T1[i4][m]*Anx[jb+s][m]
            {
                float a0 = (i4 == jb    ) ? 0.08f : 0.f;
                float a1 = (i4 == jb + 1) ? 0.08f : 0.f;
                float a2 = (i4 == jb + 2) ? 0.08f : 0.f;
                float a3 = (i4 == jb + 3) ? 0.08f : 0.f;
                #pragma unroll
                for (int m4 = 0; m4 < 32; m4 += 4) {
                    const float4 t4 = *(const float4*)&T1b[i4*36 + m4];
                    a0 += t4.x*Anx[(jb    )*33 + m4]     + t4.y*Anx[(jb    )*33 + m4 + 1]
                        + t4.z*Anx[(jb    )*33 + m4 + 2] + t4.w*Anx[(jb    )*33 + m4 + 3];
                    a1 += t4.x*Anx[(jb + 1)*33 + m4]     + t4.y*Anx[(jb + 1)*33 + m4 + 1]
                        + t4.z*Anx[(jb + 1)*33 + m4 + 2] + t4.w*Anx[(jb + 1)*33 + m4 + 3];
                    a2 += t4.x*Anx[(jb + 2)*33 + m4]     + t4.y*Anx[(jb + 2)*33 + m4 + 1]
                        + t4.z*Anx[(jb + 2)*33 + m4 + 2] + t4.w*Anx[(jb + 2)*33 + m4 + 3];
                    a3 += t4.x*Anx[(jb + 3)*33 + m4]     + t4.y*Anx[(jb + 3)*33 + m4 + 1]
                        + t4.z*Anx[(jb + 3)*33 + m4 + 2] + t4.w*Anx[(jb + 3)*33 + m4 + 3];
                }
                sigp[i4*33 + jb]     = a0;
                sigp[i4*33 + jb + 1] = a1;
                sigp[i4*33 + jb + 2] = a2;
                sigp[i4*33 + jb + 3] = a3;
                float4 r = {a0, a1, a2, a3};
                *(float4*)(g_sp + (size_t)btt*1024 + i4*32 + jb) = r;
            }
            __syncthreads();   // B8
        }
    }
}

// =====================================================================
// Kernel 4: batched solves X = sp^{-1} T1 — TWO solves per CTA
// (128 threads each; grid halves; each CTA barrier serves 2 solves).
// Per solve: c = t128>>1 (64 cols), q = t128&1 (16 rows in regs).
// Same element-wise GJ arithmetic as the round-10-verified version.
// =====================================================================
__global__ void __launch_bounds__(256)
solve_kernel()
{
    const int tid = threadIdx.x;
    const int s = tid >> 7;                 // sub-solve 0/1
    const int t128 = tid & 127;
    const int c = t128 >> 1, q = t128 & 1;  // column, row-half (16 rows)

    const int lin = blockIdx.x*2 + s;       // 0 .. Bq*(Tq-1)-1
    const int b = lin / (Tq - 1), t = lin % (Tq - 1);
    const size_t bt = (size_t)b*Tq + t;

    __shared__ float Tsh[2][32*33];
    __shared__ float sfac[2][2][32];
    __shared__ float spinv[2][2];

    // stage T1 coalesced -> shared (stride 33)
    #pragma unroll
    for (int k = 0; k < 8; k++) {
        int e = t128 + 128*k, i = e >> 5, j = e & 31;
        Tsh[s][i*33 + j] = g_T1s[bt*1024 + e];
    }

    float reg[16];
    if (c < 32) {
        // sp symmetric: column c == row c (contiguous) -> 4 float4 loads
        const float4* bp = (const float4*)(g_sp + bt*1024 + c*32 + q*16);
        #pragma unroll
        for (int k = 0; k < 4; k++) {
            float4 r4 = bp[k];
            reg[k*4]     = r4.x; reg[k*4 + 1] = r4.y;
            reg[k*4 + 2] = r4.z; reg[k*4 + 3] = r4.w;
        }
    }
    // pivot-0 prep: column 0 snapshot + reciprocal
    if (c == 0) {
        #pragma unroll
        for (int i = 0; i < 16; i++) sfac[s][0][q*16 + i] = reg[i];
        if (q == 0) spinv[s][0] = 1.f/reg[0];
    }
    __syncthreads();
    if (c >= 32) {
        #pragma unroll
        for (int i = 0; i < 16; i++) reg[i] = Tsh[s][(q*16 + i)*33 + (c - 32)];
    }

    #pragma unroll
    for (int p = 0; p < 32; p++) {
        const int pb = p & 1;
        const float piv = spinv[s][pb];
        float fac[16];
        #pragma unroll
        for (int i = 0; i < 16; i++) fac[i] = sfac[s][pb][q*16 + i];
        // row-p element of my column (pre-update), from lane q = p>>4 (width 2)
        float m_pc = __shfl_sync(0xffffffffu, reg[p & 15], p >> 4, 2);
        float mn = m_pc * piv;
        if (c > p) {
            #pragma unroll
            for (int i = 0; i < 16; i++) {
                int r = q*16 + i;
                reg[i] = (r == p) ? mn : (reg[i] - fac[i]*mn);
            }
            if (p < 31 && c == p + 1) {
                #pragma unroll
                for (int i = 0; i < 16; i++) sfac[s][pb ^ 1][q*16 + i] = reg[i];
                if (q == ((p + 1) >> 4)) spinv[s][pb ^ 1] = 1.f/reg[(p + 1) & 15];
            }
        }
        __syncthreads();
    }

    // stage X through shared, write coalesced
    if (c >= 32) {
        #pragma unroll
        for (int i = 0; i < 16; i++) Tsh[s][(q*16 + i)*33 + (c - 32)] = reg[i];
    }
    __syncthreads();
    #pragma unroll
    for (int k = 0; k < 8; k++) {
        int e = t128 + 128*k, i = e >> 5, j = e & 31;
        g_X[bt*1024 + e] = Tsh[s][i*33 + j];
    }
}

// =====================================================================
// Kernel 5: RTS backward (round-13 verified, unchanged — register
// prefetch pipeline, 3 barriers/step).
// =====================================================================
__global__ void __launch_bounds__(256)
bwd_kernel(float* __restrict__ out_mu, float* __restrict__ out_sig)
{
    __shared__ __align__(16) float X[1024], D[1024], G[1024], Ssn[1024];
    __shared__ float sdm[ZD], smf[ZD], sxv[ZD], smusn[ZD];

    const int b = blockIdx.x, tid = threadIdx.x;
    const int i4 = tid >> 3, jb = (tid & 7) << 2;

    float4 rX, rSp, rSf;       // prefetched values for the CURRENT step
    float  rmp = 0.f, rmf = 0.f;

    {
        const size_t btl = (size_t)b*Tq + (Tq - 1);
        ((float4*)Ssn)[tid] = ((const float4*)(g_sigf + btl*1024))[tid];
        if (tid < ZD) smusn[tid] = g_muf[btl*ZD + tid];
        const size_t bt0 = (size_t)b*Tq + (Tq - 2);
        rX  = ((const float4*)(g_X    + bt0*1024))[tid];
        rSp = ((const float4*)(g_sp   + bt0*1024))[tid];
        rSf = ((const float4*)(g_sigf + bt0*1024))[tid];
        if (tid < ZD) { rmp = g_mp[bt0*ZD + tid]; rmf = g_muf[bt0*ZD + tid]; }
    }
    __syncthreads();

    for (int t = Tq - 2; t >= 0; t--) {
        const size_t bt = (size_t)b*Tq + t;
        ((float4*)X)[tid] = rX;
        {
            float4 s = ((const float4*)Ssn)[tid];
            float4 d = {s.x - rSp.x, s.y - rSp.y, s.z - rSp.z, s.w - rSp.w};
            ((float4*)D)[tid] = d;
        }
        if (tid < ZD) {
            sdm[tid] = smusn[tid] - rmp;
            smf[tid] = rmf;
        }
        __syncthreads();

        float4 nX, nSp, nSf; float nmp = 0.f, nmf = 0.f;
        if (t > 0) {
            const size_t btn = bt - 1;
            nX  = ((const float4*)(g_X    + btn*1024))[tid];
            nSp = ((const float4*)(g_sp   + btn*1024))[tid];
            nSf = ((const float4*)(g_sigf + btn*1024))[tid];
            if (tid < ZD) { nmp = g_mp[btn*ZD + tid]; nmf = g_muf[btn*ZD + tid]; }
        }
        {
            float g0 = 0, g1 = 0, g2 = 0, g3 = 0;
            #pragma unroll
            for (int m = 0; m < 32; m++) {
                float dv = D[i4*32 + m];
                const float4 xm = *(const float4*)&X[m*32 + jb];
                g0 += dv*xm.x; g1 += dv*xm.y; g2 += dv*xm.z; g3 += dv*xm.w;
            }
            G[i4*32 + jb] = g0; G[i4*32 + jb + 1] = g1;
            G[i4*32 + jb + 2] = g2; G[i4*32 + jb + 3] = g3;
        }
        if (tid < ZD) {
            float v = 0.f;
            #pragma unroll
            for (int k = 0; k < 32; k++) v += X[k*32 + tid]*sdm[k];
            sxv[tid] = v;
        }
        __syncthreads();

        {
            float4 acc = rSf;
            #pragma unroll
            for (int k = 0; k < 32; k++) {
                float xk = X[k*32 + i4];
                const float4 g4 = *(const float4*)&G[k*32 + jb];
                acc.x += xk*g4.x; acc.y += xk*g4.y; acc.z += xk*g4.z; acc.w += xk*g4.w;
            }
            ((float4*)(out_sig + bt*1024))[tid] = acc;
            ((float4*)Ssn)[tid] = acc;
        }
        if (tid < ZD) {
            float v = smf[tid] + sxv[tid];
            out_mu[bt*ZD + tid] = v;
            smusn[tid] = v;
        }
        __syncthreads();

        rX = nX; rSp = nSp; rSf = nSf; rmp = nmp; rmf = nmf;
    }
}

// =====================================================================
extern "C" void kernel_launch(void* const* d_in, const int* in_sizes, int n_in,
                              void* d_out, int out_size)
{
    const float* a       = (const float*)d_in[0];
    const float* a1      = (const float*)d_in[1];
    const float* W_ih    = (const float*)d_in[2];
    const float* W_hh    = (const float*)d_in[3];
    const float* b_ih    = (const float*)d_in[4];
    const float* b_hh    = (const float*)d_in[5];
    const float* W_alpha = (const float*)d_in[6];
    const float* b_alpha = (const float*)d_in[7];
    const float* Ag      = (const float*)d_in[8];
    const float* Cg      = (const float*)d_in[9];

    float* out    = (float*)d_out;
    float* out_mu = out;                              // [B,T,32]
    float* out_sg = out_mu + (size_t)BT*ZD;           // [B,T,32,32]
    float* out_A  = out_sg + (size_t)BT*ZD*ZD;        // [B,T,32,32]
    float* out_C  = out_A  + (size_t)BT*ZD*ZD;        // [B,T,8,32]

    lstm_kernel<<<Bq, 256>>>(a, a1, W_ih, W_hh, b_ih, b_hh, W_alpha, b_alpha);
    mix_kernel<<<BT/128, 256>>>(Ag, Cg, out_A, out_C);
    fwd_kernel<<<Bq, 256>>>(a, out_mu, out_sg, out_A, out_C);
    solve_kernel<<<Bq*(Tq - 1)/2, 256>>>();
    bwd_kernel<<<Bq, 256>>>(out_mu, out_sg);
}

// round 17
// speedup vs baseline: 1.2963x; 1.0141x over previous
#include <cuda_runtime.h>

// ---------------- problem constants ----------------
#define Bq   256
#define Tq   128
#define AD   8
#define ZD   32
#define KM   16
#define HIDq 50
#define BT   (Bq*Tq)

// ---------------- device scratch ----------------
__device__ float g_w[BT*KM];
__device__ float g_sigf[(size_t)BT*1024];   // Sigma_f[t]
__device__ float g_T1s[(size_t)BT*1024];    // T1 = A_{t+1} Sigma_f[t]   (slot t, t<=T-2)
__device__ float g_sp[(size_t)BT*1024];     // Sigma_pred[t+1]           (slot t, t<=T-2)
__device__ float g_X[(size_t)BT*1024];      // X = sp^{-1} T1 (= J^T)    (slot t, t<=T-2)
__device__ float g_muf[BT*ZD];              // mu_f[t]
__device__ float g_mp[BT*ZD];               // mu_pred[t+1]              (slot t, t<=T-2)

// =====================================================================
// Kernel 1: LSTM over T + softmax mixture weights (round-16 verified).
// =====================================================================
__global__ void __launch_bounds__(256)
lstm_kernel(const float* __restrict__ a,  const float* __restrict__ a1,
            const float* __restrict__ W_ih, const float* __restrict__ W_hh,
            const float* __restrict__ b_ih, const float* __restrict__ b_hh,
            const float* __restrict__ W_alpha, const float* __restrict__ b_alpha)
{
    __shared__ float sWa[KM*HIDq];
    __shared__ float sh[HIDq], sc[HIDq], sx[2][AD], sg[200];

    const int b = blockIdx.x, tid = threadIdx.x;

    float wi[AD]; float bg = 0.f;
    float whh[HIDq];
    if (tid < 200) {
        #pragma unroll
        for (int j = 0; j < AD; j++) wi[j] = W_ih[tid*AD + j];
        bg = b_ih[tid] + b_hh[tid];
        #pragma unroll
        for (int j = 0; j < HIDq; j++) whh[j] = W_hh[tid*HIDq + j];
    }
    for (int i = tid; i < KM*HIDq; i += 256) sWa[i] = W_alpha[i];
    if (tid < HIDq) { sh[tid] = 0.f; sc[tid] = 0.f; }
    if (tid < AD)   sx[0][tid] = a1[tid];
    __syncthreads();

    for (int t = 0; t < Tq; t++) {
        const float* x = sx[t & 1];
        if (tid < 200) {
            float a0 = bg, a1_ = 0.f, a2 = 0.f, a3 = 0.f;
            #pragma unroll
            for (int j = 0; j < AD; j++) a0 += x[j]*wi[j];
            #pragma unroll
            for (int j = 0; j < 48; j += 4) {
                a0  += sh[j  ]*whh[j  ];
                a1_ += sh[j+1]*whh[j+1];
                a2  += sh[j+2]*whh[j+2];
                a3  += sh[j+3]*whh[j+3];
            }
            a0  += sh[48]*whh[48];
            a1_ += sh[49]*whh[49];
            sg[tid] = (a0 + a1_) + (a2 + a3);
        } else if (tid < 208 && t < Tq - 1) {
            sx[(t + 1) & 1][tid - 200] = a[(b*Tq + t)*AD + (tid - 200)];
        }
        __syncthreads();                 // B2
        if (tid < HIDq) {
            float ig = 1.f/(1.f + __expf(-sg[tid]));
            float fg = 1.f/(1.f + __expf(-sg[HIDq + tid]));
            float gg = tanhf(sg[2*HIDq + tid]);
            float og = 1.f/(1.f + __expf(-sg[3*HIDq + tid]));
            float c  = fg*sc[tid] + ig*gg;
            sc[tid] = c;
            sh[tid] = og*tanhf(c);
        }
        __syncthreads();                 // B3
        if (tid < 32) {
            float logit = -1e30f;
            if (tid < KM) {
                logit = b_alpha[tid];
                #pragma unroll
                for (int j = 0; j < HIDq; j++) logit += sh[j]*sWa[tid*HIDq + j];
            }
            float m = logit;
            #pragma unroll
            for (int d = 8; d; d >>= 1)
                m = fmaxf(m, __shfl_xor_sync(0xffffffffu, m, d, 16));
            float e = __expf(logit - m);
            float s = e;
            #pragma unroll
            for (int d = 8; d; d >>= 1)
                s += __shfl_xor_sync(0xffffffffu, s, d, 16);
            if (tid < KM) g_w[(b*Tq + t)*KM + tid] = e/s;
        }
    }
}

// =====================================================================
// Kernel 2: A_t/C_t mixing (verified, unchanged).
// =====================================================================
__global__ void __launch_bounds__(256)
mix_kernel(const float* __restrict__ Ag, const float* __restrict__ Cg,
           float* __restrict__ outA, float* __restrict__ outC)
{
    __shared__ float sw[128*KM];
    const int tid = threadIdx.x;
    const int r0  = blockIdx.x * 128;
    for (int i = tid; i < 128*KM; i += 256) sw[i] = g_w[r0*KM + i];
    __syncthreads();

    for (int c = tid; c < 1280; c += 256) {
        float av[KM];
        if (c < 1024) {
            #pragma unroll
            for (int k = 0; k < KM; k++) av[k] = Ag[k*1024 + c];
            for (int r = 0; r < 128; r++) {
                float acc = 0.f;
                #pragma unroll
                for (int k = 0; k < KM; k++) acc += sw[r*KM + k]*av[k];
                outA[(size_t)(r0 + r)*1024 + c] = acc;
            }
        } else {
            const int cc = c - 1024;
            #pragma unroll
            for (int k = 0; k < KM; k++) av[k] = Cg[k*256 + cc];
            for (int r = 0; r < 128; r++) {
                float acc = 0.f;
                #pragma unroll
                for (int k = 0; k < KM; k++) acc += sw[r*KM + k]*av[k];
                outC[(r0 + r)*256 + cc] = acc;
            }
        }
    }
}

// =====================================================================
// Kernel 3: Kalman forward filter (round-16 verified, unchanged).
// Kg from Pt (rows of sigp) — load-bearing for stability.
// =====================================================================
__global__ void __launch_bounds__(256)
fwd_kernel(const float* __restrict__ a,
           float* __restrict__ out_mu, float* __restrict__ out_sig,
           const float* __restrict__ outA, const float* __restrict__ outC)
{
    __shared__ float sAbuf[2*1056];                 // ping-pong A (stride 33)
    __shared__ float sC2[2][256];                   // double-buffered C_t [8][32]
    __shared__ float sigp[1056];                    // sig_pred (stride 33)
    __shared__ __align__(16) float sigf[1024];      // sig_filt (stride 32)
    __shared__ __align__(16) float big[1024];       // M1 | Pt | (unused) | aug8
    __shared__ __align__(16) float T1b[32*36];      // T1 (stride 36)
    __shared__ float sAmu[ZD], serr[AD], smu[ZD];

    const int b = blockIdx.x, tid = threadIdx.x;
    const int i4 = tid >> 3;                // tiled-output row (0..31)
    const int jb = (tid & 7) << 2;          // tiled-output col block (x4)
    const bool early_pf = !(tid < 32 || (tid >= 64 && tid < 72));

    // ---- init: sig_pred = 20*I, mu = 0, load A_t[b][0], C_t[b][0] ----
    for (int e = tid; e < 1024; e += 256) {
        int i = e >> 5, j = e & 31;
        sigp[i*33 + j] = (i == j) ? 20.f : 0.f;
        sAbuf[i*33 + j] = outA[(size_t)(b*Tq)*1024 + e];
    }
    sC2[0][tid] = outC[(size_t)(b*Tq)*256 + tid];
    if (tid < ZD) smu[tid] = 0.f;
    __syncthreads();

    for (int t = 0; t < Tq; t++) {
        float* Ac  = sAbuf + (t & 1)*1056;
        float* Anx = sAbuf + ((t + 1) & 1)*1056;
        const float* sC  = sC2[t & 1];
        float*       sCn = sC2[(t + 1) & 1];
        const int btt = b*Tq + t;

        // ---- TOP: issue next-step prefetch LDGs ----
        float4 rA; float rC = 0.f, ry = 0.f;
        if (t < Tq - 1) {
            rA = *(const float4*)(outA + (size_t)(btt + 1)*1024 + i4*32 + jb);
            rC = outC[(size_t)(btt + 1)*256 + tid];
        }
        if (tid >= 64 && tid < 72) ry = a[(size_t)btt*AD + (tid - 64)];

        // B2 phase: M1 = C @ sigp ; Pt[l][j] = (sigp C^T)[j][l]
        //           + Amu = Ac @ mu (tid<32)
        {
            int l = tid >> 5, j = tid & 31;
            float acc = 0.f;
            #pragma unroll
            for (int m = 0; m < 32; m++) acc += sC[l*32 + m]*sigp[m*33 + j];
            big[l*32 + j] = acc;
            float acc2 = 0.f;
            #pragma unroll
            for (int m = 0; m < 32; m++) acc2 += sigp[j*33 + m]*sC[l*32 + m];
            big[256 + l*32 + j] = acc2;
        }
        if (tid < ZD) {
            float acc = 0.f;
            #pragma unroll
            for (int m = 0; m < 32; m++) acc += Ac[tid*33 + m]*smu[m];
            sAmu[tid] = acc;
            if (t > 0) g_mp[(btt - 1)*ZD + tid] = acc;  // mu_pred[t] at slot t-1
        }
        __syncthreads();   // B2

        // B34 phase: warp0 = S aug then invert; tid 64..71 = err;
        //            remaining threads STS their prefetched A/C rows
        if (tid < 32) {
            #pragma unroll
            for (int h = 0; h < 2; h++) {
                int o = tid + 32*h;
                int l = o >> 3, n = o & 7;
                float acc = 0.f;
                #pragma unroll
                for (int m = 0; m < 32; m++) acc += big[l*32 + m]*sC[n*32 + m];
                big[768 + l*16 + n]     = acc + ((l == n) ? 0.03f : 0.f);
                big[768 + l*16 + 8 + n] = (l == n) ? 1.f : 0.f;
            }
            __syncwarp();
            // invert 8x8 SPD (Gauss-Jordan, verified)
            int r = tid >> 2, c0 = (tid & 3)*4;
            #pragma unroll
            for (int p = 0; p < 8; p++) {
                float fc  = big[768 + r*16 + p];
                float p0 = big[768 + p*16 + c0];
                float p1 = big[768 + p*16 + c0 + 1];
                float p2 = big[768 + p*16 + c0 + 2];
                float p3 = big[768 + p*16 + c0 + 3];
                float pd = big[768 + p*16 + p];
                __syncwarp();
                float pinv = 1.f/pd;
                if (r == p) {
                    big[768 + r*16 + c0]     = p0*pinv;
                    big[768 + r*16 + c0 + 1] = p1*pinv;
                    big[768 + r*16 + c0 + 2] = p2*pinv;
                    big[768 + r*16 + c0 + 3] = p3*pinv;
                } else {
                    float f = fc*pinv;
                    big[768 + r*16 + c0]     -= f*p0;
                    big[768 + r*16 + c0 + 1] -= f*p1;
                    big[768 + r*16 + c0 + 2] -= f*p2;
                    big[768 + r*16 + c0 + 3] -= f*p3;
                }
                __syncwarp();
            }
        } else if (tid >= 64 && tid < 72) {
            int l = tid - 64;
            float acc = 0.f;
            #pragma unroll
            for (int m = 0; m < 32; m++) acc += sC[l*32 + m]*sAmu[m];
            serr[l] = ry - acc;
        } else if (t < Tq - 1) {
            // early prefetch STS (overlaps warp0's inversion)
            Anx[i4*33 + jb]     = rA.x;
            Anx[i4*33 + jb + 1] = rA.y;
            Anx[i4*33 + jb + 2] = rA.z;
            Anx[i4*33 + jb + 3] = rA.w;
            sCn[tid] = rC;
        }
        __syncthreads();   // B34

        // B6 phase (tiled): local kg; sigf row i4 cols jb..jb+3;
        // leftover prefetch STS (warp0 + err group); mu_f (tid<32)
        {
            float kg[8];
            #pragma unroll
            for (int l = 0; l < 8; l++) {
                float acc = 0.f;
                #pragma unroll
                for (int n = 0; n < 8; n++)
                    acc += big[256 + n*32 + i4]*big[768 + n*16 + 8 + l];
                kg[l] = acc;
            }
            float4 v = {sigp[i4*33 + jb],     sigp[i4*33 + jb + 1],
                        sigp[i4*33 + jb + 2], sigp[i4*33 + jb + 3]};
            #pragma unroll
            for (int l = 0; l < 8; l++) {
                float k = kg[l];
                const float4 m = *(const float4*)&big[l*32 + jb];
                v.x -= k*m.x; v.y -= k*m.y; v.z -= k*m.z; v.w -= k*m.w;
            }
            *(float4*)&sigf[i4*32 + jb] = v;
            *(float4*)(g_sigf + (size_t)btt*1024 + i4*32 + jb) = v;
            if (t == Tq - 1) *(float4*)(out_sig + (size_t)btt*1024 + i4*32 + jb) = v;
            if (t < Tq - 1 && !early_pf) {
                Anx[i4*33 + jb]     = rA.x;
                Anx[i4*33 + jb + 1] = rA.y;
                Anx[i4*33 + jb + 2] = rA.z;
                Anx[i4*33 + jb + 3] = rA.w;
                sCn[tid] = rC;
            }
        }
        if (tid < ZD) {
            float v = sAmu[tid];
            #pragma unroll
            for (int l = 0; l < 8; l++) {
                float kv = 0.f;
                #pragma unroll
                for (int n = 0; n < 8; n++)
                    kv += big[256 + n*32 + tid]*big[768 + n*16 + 8 + l];
                v += kv*serr[l];
            }
            smu[tid] = v;
            g_muf[btt*ZD + tid] = v;
            if (t == Tq - 1) out_mu[btt*ZD + tid] = v;
        }
        __syncthreads();   // B6

        if (t < Tq - 1) {
            // B7 phase (tiled): T1[i4][jb..jb+3] = sum_m Anx[i4][m]*sigf[m][jb..+3]
            {
                float x0 = 0.f, x1 = 0.f, x2 = 0.f, x3 = 0.f;
                #pragma unroll
                for (int m = 0; m < 32; m++) {
                    float av = Anx[i4*33 + m];
                    const float4 s = *(const float4*)&sigf[m*32 + jb];
                    x0 += av*s.x; x1 += av*s.y; x2 += av*s.z; x3 += av*s.w;
                }
                T1b[i4*36 + jb]     = x0;
                T1b[i4*36 + jb + 1] = x1;
                T1b[i4*36 + jb + 2] = x2;
                T1b[i4*36 + jb + 3] = x3;
                float4 r = {x0, x1, x2, x3};
                *(float4*)(g_T1s + (size_t)btt*1024 + i4*32 + jb) = r;
            }
            __syncthreads();   // B7

            // B8 phase (tiled): sigp[i4][jb+s] = Q + sum_m T1[i4][m]*Anx[jb+s][m]
            {
                float a0 = (i4 == jb    ) ? 0.08f : 0.f;
                float a1 = (i4 == jb + 1) ? 0.08f : 0.f;
                float a2 = (i4 == jb + 2) ? 0.08f : 0.f;
                float a3 = (i4 == jb + 3) ? 0.08f : 0.f;
                #pragma unroll
                for (int m4 = 0; m4 < 32; m4 += 4) {
                    const float4 t4 = *(const float4*)&T1b[i4*36 + m4];
                    a0 += t4.x*Anx[(jb    )*33 + m4]     + t4.y*Anx[(jb    )*33 + m4 + 1]
                        + t4.z*Anx[(jb    )*33 + m4 + 2] + t4.w*Anx[(jb    )*33 + m4 + 3];
                    a1 += t4.x*Anx[(jb + 1)*33 + m4]     + t4.y*Anx[(jb + 1)*33 + m4 + 1]
                        + t4.z*Anx[(jb + 1)*33 + m4 + 2] + t4.w*Anx[(jb + 1)*33 + m4 + 3];
                    a2 += t4.x*Anx[(jb + 2)*33 + m4]     + t4.y*Anx[(jb + 2)*33 + m4 + 1]
                        + t4.z*Anx[(jb + 2)*33 + m4 + 2] + t4.w*Anx[(jb + 2)*33 + m4 + 3];
                    a3 += t4.x*Anx[(jb + 3)*33 + m4]     + t4.y*Anx[(jb + 3)*33 + m4 + 1]
                        + t4.z*Anx[(jb + 3)*33 + m4 + 2] + t4.w*Anx[(jb + 3)*33 + m4 + 3];
                }
                sigp[i4*33 + jb]     = a0;
                sigp[i4*33 + jb + 1] = a1;
                sigp[i4*33 + jb + 2] = a2;
                sigp[i4*33 + jb + 3] = a3;
                float4 r = {a0, a1, a2, a3};
                *(float4*)(g_sp + (size_t)btt*1024 + i4*32 + jb) = r;
            }
            __syncthreads();   // B8
        }
    }
}

// =====================================================================
// Kernel 4: batched solves X = sp^{-1} T1 — TWO solves per CTA
// (round-16 verified, unchanged).
// =====================================================================
__global__ void __launch_bounds__(256)
solve_kernel()
{
    const int tid = threadIdx.x;
    const int s = tid >> 7;                 // sub-solve 0/1
    const int t128 = tid & 127;
    const int c = t128 >> 1, q = t128 & 1;  // column, row-half (16 rows)

    const int lin = blockIdx.x*2 + s;       // 0 .. Bq*(Tq-1)-1
    const int b = lin / (Tq - 1), t = lin % (Tq - 1);
    const size_t bt = (size_t)b*Tq + t;

    __shared__ float Tsh[2][32*33];
    __shared__ float sfac[2][2][32];
    __shared__ float spinv[2][2];

    // stage T1 coalesced -> shared (stride 33)
    #pragma unroll
    for (int k = 0; k < 8; k++) {
        int e = t128 + 128*k, i = e >> 5, j = e & 31;
        Tsh[s][i*33 + j] = g_T1s[bt*1024 + e];
    }

    float reg[16];
    if (c < 32) {
        // sp symmetric: column c == row c (contiguous) -> 4 float4 loads
        const float4* bp = (const float4*)(g_sp + bt*1024 + c*32 + q*16);
        #pragma unroll
        for (int k = 0; k < 4; k++) {
            float4 r4 = bp[k];
            reg[k*4]     = r4.x; reg[k*4 + 1] = r4.y;
            reg[k*4 + 2] = r4.z; reg[k*4 + 3] = r4.w;
        }
    }
    // pivot-0 prep: column 0 snapshot + reciprocal
    if (c == 0) {
        #pragma unroll
        for (int i = 0; i < 16; i++) sfac[s][0][q*16 + i] = reg[i];
        if (q == 0) spinv[s][0] = 1.f/reg[0];
    }
    __syncthreads();
    if (c >= 32) {
        #pragma unroll
        for (int i = 0; i < 16; i++) reg[i] = Tsh[s][(q*16 + i)*33 + (c - 32)];
    }

    #pragma unroll
    for (int p = 0; p < 32; p++) {
        const int pb = p & 1;
        const float piv = spinv[s][pb];
        float fac[16];
        #pragma unroll
        for (int i = 0; i < 16; i++) fac[i] = sfac[s][pb][q*16 + i];
        // row-p element of my column (pre-update), from lane q = p>>4 (width 2)
        float m_pc = __shfl_sync(0xffffffffu, reg[p & 15], p >> 4, 2);
        float mn = m_pc * piv;
        if (c > p) {
            #pragma unroll
            for (int i = 0; i < 16; i++) {
                int r = q*16 + i;
                reg[i] = (r == p) ? mn : (reg[i] - fac[i]*mn);
            }
            if (p < 31 && c == p + 1) {
                #pragma unroll
                for (int i = 0; i < 16; i++) sfac[s][pb ^ 1][q*16 + i] = reg[i];
                if (q == ((p + 1) >> 4)) spinv[s][pb ^ 1] = 1.f/reg[(p + 1) & 15];
            }
        }
        __syncthreads();
    }

    // stage X through shared, write coalesced
    if (c >= 32) {
        #pragma unroll
        for (int i = 0; i < 16; i++) Tsh[s][(q*16 + i)*33 + (c - 32)] = reg[i];
    }
    __syncthreads();
    #pragma unroll
    for (int k = 0; k < 8; k++) {
        int e = t128 + 128*k, i = e >> 5, j = e & 31;
        g_X[bt*1024 + e] = Tsh[s][i*33 + j];
    }
}

// =====================================================================
// Kernel 5: RTS backward — 2 barriers/step. pass0 eliminated:
// pass B of step t+1 writes D(t) = acc - sp(t) and X(t) directly
// (X double-buffered; D single — last read before barrier A).
// sdm handled as a warp-0 syncwarp mini-phase inside pass A;
// smf/xv/smusn held in registers. Identical arithmetic per output.
// =====================================================================
__global__ void __launch_bounds__(256)
bwd_kernel(float* __restrict__ out_mu, float* __restrict__ out_sig)
{
    __shared__ __align__(16) float Xb[2][1024], D[1024], G[1024];
    __shared__ float sdm[ZD];

    const int b = blockIdx.x, tid = threadIdx.x;
    const int i4 = tid >> 3, jb = (tid & 7) << 2;

    float4 rSf;                 // sigf for CURRENT step
    float  rmp = 0.f, rmf = 0.f;
    float  musn_r = 0.f;        // lane-local mu_sn (valid for tid<32)
    int    cur = 0;

    {
        const size_t btl = (size_t)b*Tq + (Tq - 1);
        float4 slast = ((const float4*)(g_sigf + btl*1024))[tid];
        if (tid < ZD) musn_r = g_muf[btl*ZD + tid];
        const size_t bt0 = btl - 1;                 // t = Tq-2
        float4 rX  = ((const float4*)(g_X  + bt0*1024))[tid];
        float4 rSp = ((const float4*)(g_sp + bt0*1024))[tid];
        rSf = ((const float4*)(g_sigf + bt0*1024))[tid];
        if (tid < ZD) { rmp = g_mp[bt0*ZD + tid]; rmf = g_muf[bt0*ZD + tid]; }
        ((float4*)Xb[0])[tid] = rX;
        float4 d = {slast.x - rSp.x, slast.y - rSp.y,
                    slast.z - rSp.z, slast.w - rSp.w};
        ((float4*)D)[tid] = d;
    }
    __syncthreads();

    for (int t = Tq - 2; t >= 0; t--) {
        const size_t bt = (size_t)b*Tq + t;
        const float* X = Xb[cur];

        // pass A: issue next prefetch FIRST, then G = D @ X ; sdm/xv (warp0)
        float4 nX, nSp, nSf; float nmp = 0.f, nmf = 0.f;
        if (t > 0) {
            const size_t btn = bt - 1;
            nX  = ((const float4*)(g_X    + btn*1024))[tid];
            nSp = ((const float4*)(g_sp   + btn*1024))[tid];
            nSf = ((const float4*)(g_sigf + btn*1024))[tid];
            if (tid < ZD) { nmp = g_mp[btn*ZD + tid]; nmf = g_muf[btn*ZD + tid]; }
        }
        {
            float g0 = 0, g1 = 0, g2 = 0, g3 = 0;
            #pragma unroll
            for (int m = 0; m < 32; m++) {
                float dv = D[i4*32 + m];
                const float4 xm = *(const float4*)&X[m*32 + jb];
                g0 += dv*xm.x; g1 += dv*xm.y; g2 += dv*xm.z; g3 += dv*xm.w;
            }
            G[i4*32 + jb] = g0; G[i4*32 + jb + 1] = g1;
            G[i4*32 + jb + 2] = g2; G[i4*32 + jb + 3] = g3;
        }
        float xv = 0.f;
        if (tid < ZD) {
            sdm[tid] = musn_r - rmp;
            __syncwarp();
            #pragma unroll
            for (int k = 0; k < 32; k++) xv += X[k*32 + tid]*sdm[k];
        }
        __syncthreads();   // barrier A

        // pass B: sig_s = rSf + X^T G -> out ; D(t-1) = acc - nSp ;
        //         X(t-1) = nX ; mu_s = rmf + xv
        {
            float4 acc = rSf;
            #pragma unroll
            for (int k = 0; k < 32; k++) {
                float xk = X[k*32 + i4];
                const float4 g4 = *(const float4*)&G[k*32 + jb];
                acc.x += xk*g4.x; acc.y += xk*g4.y; acc.z += xk*g4.z; acc.w += xk*g4.w;
            }
            ((float4*)(out_sig + bt*1024))[tid] = acc;
            if (t > 0) {
                float4 d = {acc.x - nSp.x, acc.y - nSp.y,
                            acc.z - nSp.z, acc.w - nSp.w};
                ((float4*)D)[tid] = d;
                ((float4*)Xb[cur ^ 1])[tid] = nX;
            }
        }
        if (tid < ZD) {
            float v = rmf + xv;
            out_mu[bt*ZD + tid] = v;
            musn_r = v;
        }
        __syncthreads();   // barrier B

        rSf = nSf; rmp = nmp; rmf = nmf; cur ^= 1;
    }
}

// =====================================================================
extern "C" void kernel_launch(void* const* d_in, const int* in_sizes, int n_in,
                              void* d_out, int out_size)
{
    const float* a       = (const float*)d_in[0];
    const float* a1      = (const float*)d_in[1];
    const float* W_ih    = (const float*)d_in[2];
    const float* W_hh    = (const float*)d_in[3];
    const float* b_ih    = (const float*)d_in[4];
    const float* b_hh    = (const float*)d_in[5];
    const float* W_alpha = (const float*)d_in[6];
    const float* b_alpha = (const float*)d_in[7];
    const float* Ag      = (const float*)d_in[8];
    const float* Cg      = (const float*)d_in[9];

    float* out    = (float*)d_out;
    float* out_mu = out;                              // [B,T,32]
    float* out_sg = out_mu + (size_t)BT*ZD;           // [B,T,32,32]
    float* out_A  = out_sg + (size_t)BT*ZD*ZD;        // [B,T,32,32]
    float* out_C  = out_A  + (size_t)BT*ZD*ZD;        // [B,T,8,32]

    lstm_kernel<<<Bq, 256>>>(a, a1, W_ih, W_hh, b_ih, b_hh, W_alpha, b_alpha);
    mix_kernel<<<BT/128, 256>>>(Ag, Cg, out_A, out_C);
    fwd_kernel<<<Bq, 256>>>(a, out_mu, out_sg, out_A, out_C);
    solve_kernel<<<Bq*(Tq - 1)/2, 256>>>();
    bwd_kernel<<<Bq, 256>>>(out_mu, out_sg);
}